// round 1
// baseline (speedup 1.0000x reference)
#include <cuda_runtime.h>
#include <math.h>

#define NN 50000
#define EE 20000
#define MM 320000
#define WROWS 396   // 128 (gate MLP) + 12 (wqe) + 256 (V)
#define PSTR 400    // padded row stride of P
#define VOFF 140    // V columns start at 140 in P

// ---------------- scratch (device globals; no allocation allowed) ----------
__device__ float    g_P[(size_t)NN * PSTR];     // per-node projections (incl. V)
__device__ float    g_s[NN * 12];               // per-node gated logits [t][h]
__device__ float    g_alpha[MM * 4];            // per-pair alpha / ex
__device__ unsigned g_mx[EE * 4];               // segment max (ordered-uint)
__device__ float    g_den[EE * 4];              // segment sum
__device__ float    g_edge[(size_t)EE * 256];   // edge features
__device__ float    g_node[(size_t)NN * 256];   // node features
__device__ float    g_h[(size_t)NN * 256];      // hidden after layer 0
__device__ float    g_wcat[2 * WROWS * 256];    // folded weights per layer
__device__ float    g_tb[2 * 4 * 3 * 32];       // folded type bias

// ---------------- helpers ---------------------------------------------------
__device__ __forceinline__ unsigned enc_f(float f) {
    unsigned b = __float_as_uint(f);
    return (b & 0x80000000u) ? ~b : (b | 0x80000000u);
}
__device__ __forceinline__ float dec_f(unsigned u) {
    return __uint_as_float((u & 0x80000000u) ? (u ^ 0x80000000u) : ~u);
}
__device__ __forceinline__ void red4(float* p, float a, float b, float c, float d) {
    asm volatile("red.global.add.v4.f32 [%0], {%1,%2,%3,%4};"
                 :: "l"(p), "f"(a), "f"(b), "f"(c), "f"(d) : "memory");
}

// ---------------- weight folding --------------------------------------------
__global__ void k_prep_wcat(const float* __restrict__ w1, const float* __restrict__ wq,
                            const float* __restrict__ wv, const float* __restrict__ ec) {
    int id = blockIdx.x * blockDim.x + threadIdx.x;
    if (id >= 2 * WROWS * 256) return;
    int d = id & 255;
    int r = (id >> 8) % WROWS;
    int l = id / (WROWS * 256);
    float val;
    if (r < 128) {                       // w1 head rows (only the IN part, stride 320)
        int h = r >> 5, k = r & 31;
        val = w1[(((l * 4 + h) * 32 + k) * 320) + d];
    } else if (r < 140) {                // wqe[h,t,d] = sum_o wq[h,o,d]*ec[h,t,o]
        int rr = r - 128, h = rr / 3, t = rr % 3;
        const float* wqp = wq + ((size_t)(l * 4 + h) * 64) * 256 + d;
        const float* ecp = ec + ((l * 4 + h) * 3 + t) * 64;
        float acc = 0.f;
        #pragma unroll 8
        for (int o = 0; o < 64; o++) acc += wqp[(size_t)o * 256] * ecp[o];
        val = acc;
    } else {                             // wv rows
        int rr = r - 140, h = rr >> 6, o = rr & 63;
        val = wv[((size_t)((l * 4 + h) * 64 + o)) * 256 + d];
    }
    g_wcat[(size_t)(l * WROWS + r) * 256 + d] = val;
}

__global__ void k_prep_tb(const float* __restrict__ b1, const float* __restrict__ tq,
                          const float* __restrict__ w1) {
    int id = blockIdx.x * blockDim.x + threadIdx.x;   // id = ((l*4+h)*3+t)*32+k
    if (id >= 2 * 4 * 3 * 32) return;
    int k = id & 31;
    int rem = id >> 5;
    int t = rem % 3;
    int lh = rem / 3;                                 // l*4+h
    float acc = b1[lh * 32 + k];
    const float* tqp = tq + (lh * 3 + t) * 64;
    const float* w1p = w1 + ((size_t)(lh * 32 + k)) * 320 + 256;
    #pragma unroll 8
    for (int d = 0; d < 64; d++) acc += tqp[d] * w1p[d];
    g_tb[id] = acc;
}

// ---------------- dense GEMM: P = h x Wcat^T --------------------------------
#define BM 64
#define BN 64
#define BK 16
__global__ __launch_bounds__(256) void k_gemm(const float* __restrict__ A, int layer) {
    __shared__ float As[BK][BM];
    __shared__ float Bs[BK][BN];
    const float* B = g_wcat + (size_t)layer * WROWS * 256;
    int tid = threadIdx.x;
    int row0 = blockIdx.y * BM;
    int col0 = blockIdx.x * BN;
    int tx = tid & 15, ty = tid >> 4;
    int lr = tid >> 2;
    int lc = (tid & 3) * 4;
    float acc[4][4] = {};
    for (int kk = 0; kk < 256; kk += BK) {
        int ar = row0 + lr;
        float4 av = make_float4(0.f, 0.f, 0.f, 0.f);
        if (ar < NN) av = *(const float4*)(A + (size_t)ar * 256 + kk + lc);
        As[lc + 0][lr] = av.x; As[lc + 1][lr] = av.y;
        As[lc + 2][lr] = av.z; As[lc + 3][lr] = av.w;
        int br = col0 + lr;
        float4 bv = make_float4(0.f, 0.f, 0.f, 0.f);
        if (br < WROWS) bv = *(const float4*)(B + (size_t)br * 256 + kk + lc);
        Bs[lc + 0][lr] = bv.x; Bs[lc + 1][lr] = bv.y;
        Bs[lc + 2][lr] = bv.z; Bs[lc + 3][lr] = bv.w;
        __syncthreads();
        #pragma unroll
        for (int k = 0; k < BK; k++) {
            float a[4], b[4];
            #pragma unroll
            for (int i = 0; i < 4; i++) a[i] = As[k][ty * 4 + i];
            #pragma unroll
            for (int j = 0; j < 4; j++) b[j] = Bs[k][tx * 4 + j];
            #pragma unroll
            for (int i = 0; i < 4; i++)
                #pragma unroll
                for (int j = 0; j < 4; j++)
                    acc[i][j] += a[i] * b[j];
        }
        __syncthreads();
    }
    #pragma unroll
    for (int i = 0; i < 4; i++) {
        int r = row0 + ty * 4 + i;
        if (r >= NN) continue;
        #pragma unroll
        for (int j = 0; j < 4; j++) {
            int c = col0 + tx * 4 + j;
            if (c < WROWS) g_P[(size_t)r * PSTR + c] = acc[i][j];
        }
    }
}

// ---------------- per-node gate + logit table -------------------------------
__global__ __launch_bounds__(256) void k_post(const float* __restrict__ w2,
                                              const float* __restrict__ b2,
                                              const int* __restrict__ node_types,
                                              int l) {
    int warp = (blockIdx.x * blockDim.x + threadIdx.x) >> 5;
    int lane = threadIdx.x & 31;
    if (warp >= NN) return;
    int n = warp;
    int t = node_types[n];
    const float* Pr = g_P + (size_t)n * PSTR;
    float at[4];
    #pragma unroll
    for (int h = 0; h < 4; h++) {
        float hid = tanhf(Pr[h * 32 + lane] + g_tb[((l * 4 + h) * 3 + t) * 32 + lane]);
        float v = hid * w2[(l * 4 + h) * 32 + lane];
        #pragma unroll
        for (int off = 16; off; off >>= 1) v += __shfl_xor_sync(0xffffffffu, v, off);
        at[h] = 1.f / (1.f + __expf(-(v + b2[l * 4 + h])));
    }
    if (lane < 12) {
        int tt = lane >> 2, h = lane & 3;
        float q = Pr[128 + h * 3 + tt];
        float lr = q > 0.f ? q : 0.2f * q;
        g_s[n * 12 + lane] = lr * at[h];   // layout [n][t][h]
    }
}

// ---------------- segment softmax -------------------------------------------
__global__ __launch_bounds__(256) void k_b1(const int* __restrict__ ni,
                                            const int* __restrict__ ei,
                                            const int* __restrict__ etype) {
    int m = blockIdx.x * blockDim.x + threadIdx.x;
    if (m >= MM) return;
    int node = ni[m], edge = ei[m];
    int et = etype[edge];
    float4 a = *(const float4*)(g_s + node * 12 + et * 4);
    *(float4*)(g_alpha + (size_t)m * 4) = a;
    atomicMax(g_mx + edge * 4 + 0, enc_f(a.x));
    atomicMax(g_mx + edge * 4 + 1, enc_f(a.y));
    atomicMax(g_mx + edge * 4 + 2, enc_f(a.z));
    atomicMax(g_mx + edge * 4 + 3, enc_f(a.w));
}

__global__ __launch_bounds__(256) void k_b2(const int* __restrict__ ei) {
    int m = blockIdx.x * blockDim.x + threadIdx.x;
    if (m >= MM) return;
    int edge = ei[m];
    float4 a = *(const float4*)(g_alpha + (size_t)m * 4);
    float e0 = __expf(a.x - dec_f(g_mx[edge * 4 + 0]));
    float e1 = __expf(a.y - dec_f(g_mx[edge * 4 + 1]));
    float e2 = __expf(a.z - dec_f(g_mx[edge * 4 + 2]));
    float e3 = __expf(a.w - dec_f(g_mx[edge * 4 + 3]));
    *(float4*)(g_alpha + (size_t)m * 4) = make_float4(e0, e1, e2, e3);
    atomicAdd(g_den + edge * 4 + 0, e0);
    atomicAdd(g_den + edge * 4 + 1, e1);
    atomicAdd(g_den + edge * 4 + 2, e2);
    atomicAdd(g_den + edge * 4 + 3, e3);
}

// ---------------- scatter: node -> edge -------------------------------------
__global__ __launch_bounds__(256) void k_b3(const int* __restrict__ ni,
                                            const int* __restrict__ ei) {
    int g = blockIdx.x * blockDim.x + threadIdx.x;
    int m = g >> 5, j = g & 31;
    if (m >= MM) return;
    int node = ni[m], edge = ei[m];
    int h = j >> 3;
    float attn = g_alpha[(size_t)m * 4 + h] / g_den[edge * 4 + h];
    const float* Vr = g_P + (size_t)node * PSTR + VOFF + j * 8;
    float4 v0 = *(const float4*)(Vr);
    float4 v1 = *(const float4*)(Vr + 4);
    float* dst = g_edge + (size_t)edge * 256 + j * 8;
    red4(dst,     v0.x * attn, v0.y * attn, v0.z * attn, v0.w * attn);
    red4(dst + 4, v1.x * attn, v1.y * attn, v1.z * attn, v1.w * attn);
}

// ---------------- scatter: edge -> node -------------------------------------
__global__ __launch_bounds__(256) void k_b4(const int* __restrict__ ni,
                                            const int* __restrict__ ei) {
    int g = blockIdx.x * blockDim.x + threadIdx.x;
    int m = g >> 5, j = g & 31;
    if (m >= MM) return;
    int node = ni[m], edge = ei[m];
    int h = j >> 3;
    float attn = g_alpha[(size_t)m * 4 + h] / g_den[edge * 4 + h];
    const float* Er = g_edge + (size_t)edge * 256 + j * 8;
    float4 v0 = *(const float4*)(Er);
    float4 v1 = *(const float4*)(Er + 4);
    float* dst = g_node + (size_t)node * 256 + j * 8;
    red4(dst,     v0.x * attn, v0.y * attn, v0.z * attn, v0.w * attn);
    red4(dst + 4, v1.x * attn, v1.y * attn, v1.z * attn, v1.w * attn);
}

// ---------------- residual + LayerNorm --------------------------------------
__global__ __launch_bounds__(256) void k_ln(const float* __restrict__ hin,
                                            const float* __restrict__ g,
                                            const float* __restrict__ b,
                                            float* __restrict__ out) {
    int warp = (blockIdx.x * blockDim.x + threadIdx.x) >> 5;
    int lane = threadIdx.x & 31;
    if (warp >= NN) return;
    size_t base = (size_t)warp * 256;
    float v[8];
    float sum = 0.f;
    #pragma unroll
    for (int i = 0; i < 8; i++) {
        int c = i * 32 + lane;
        v[i] = hin[base + c] + g_node[base + c];
        sum += v[i];
    }
    #pragma unroll
    for (int off = 16; off; off >>= 1) sum += __shfl_xor_sync(0xffffffffu, sum, off);
    float mu = sum * (1.f / 256.f);
    float s2 = 0.f;
    #pragma unroll
    for (int i = 0; i < 8; i++) { float d = v[i] - mu; s2 += d * d; }
    #pragma unroll
    for (int off = 16; off; off >>= 1) s2 += __shfl_xor_sync(0xffffffffu, s2, off);
    float rstd = rsqrtf(s2 * (1.f / 256.f) + 1e-5f);
    #pragma unroll
    for (int i = 0; i < 8; i++) {
        int c = i * 32 + lane;
        out[base + c] = (v[i] - mu) * rstd * g[c] + b[c];
    }
}

// ---------------- host ------------------------------------------------------
extern "C" void kernel_launch(void* const* d_in, const int* in_sizes, int n_in,
                              void* d_out, int out_size) {
    const float* x         = (const float*)d_in[0];
    const int*   node_types= (const int*)  d_in[1];
    const int*   edge_type = (const int*)  d_in[2];
    const int*   node_idx  = (const int*)  d_in[3];
    const int*   edge_idx  = (const int*)  d_in[4];
    const float* tq        = (const float*)d_in[5];
    const float* w1        = (const float*)d_in[6];
    const float* b1        = (const float*)d_in[7];
    const float* w2        = (const float*)d_in[8];
    const float* b2        = (const float*)d_in[9];
    const float* wq        = (const float*)d_in[10];
    const float* wv        = (const float*)d_in[11];
    const float* ec        = (const float*)d_in[12];
    const float* ln_g      = (const float*)d_in[13];
    const float* ln_b      = (const float*)d_in[14];
    float* out = (float*)d_out;

    void *pmx, *pden, *pedge, *pnode, *ph;
    cudaGetSymbolAddress(&pmx,   g_mx);
    cudaGetSymbolAddress(&pden,  g_den);
    cudaGetSymbolAddress(&pedge, g_edge);
    cudaGetSymbolAddress(&pnode, g_node);
    cudaGetSymbolAddress(&ph,    g_h);
    const float* hbuf = (const float*)ph;

    k_prep_wcat<<<(2 * WROWS * 256 + 255) / 256, 256>>>(w1, wq, wv, ec);
    k_prep_tb<<<3, 256>>>(b1, tq, w1);

    for (int l = 0; l < 2; l++) {
        cudaMemsetAsync(pmx,   0, (size_t)EE * 4 * 4);
        cudaMemsetAsync(pden,  0, (size_t)EE * 4 * 4);
        cudaMemsetAsync(pedge, 0, (size_t)EE * 256 * 4);
        cudaMemsetAsync(pnode, 0, (size_t)NN * 256 * 4);

        const float* hin = l ? hbuf : x;
        dim3 gg((WROWS + BN - 1) / BN, (NN + BM - 1) / BM);
        k_gemm<<<gg, 256>>>(hin, l);
        k_post<<<(NN + 7) / 8, 256>>>(w2, b2, node_types, l);
        k_b1<<<(MM + 255) / 256, 256>>>(node_idx, edge_idx, edge_type);
        k_b2<<<(MM + 255) / 256, 256>>>(edge_idx);
        k_b3<<<(MM * 32) / 256, 256>>>(node_idx, edge_idx);
        k_b4<<<(MM * 32) / 256, 256>>>(node_idx, edge_idx);
        k_ln<<<(NN + 7) / 8, 256>>>(hin, ln_g + l * 256, ln_b + l * 256,
                                    l ? out : (float*)ph);
    }
}

// round 2
// speedup vs baseline: 1.5869x; 1.5869x over previous
#include <cuda_runtime.h>
#include <math.h>
#include <stdint.h>

#define NN 50000
#define EE 20000
#define MM 320000
#define WROWS 396   // 128 (gate MLP) + 12 (wqe) + 256 (V)
#define PSTR 400    // padded row stride of P
#define VOFF 140    // V columns start at 140 in P

// ---------------- scratch (device globals; no allocation allowed) ----------
__device__ float    g_P[(size_t)NN * PSTR];     // per-node projections (incl. V)
__device__ float    g_s[NN * 12];               // per-node gated logits [t][h]
__device__ float    g_alpha[MM * 4];            // per-pair alpha / ex / attn
__device__ unsigned g_mx[EE * 4];               // segment max (ordered-uint)
__device__ float    g_den[EE * 4];              // segment sum
__device__ float    g_edge[(size_t)EE * 256];   // edge features
__device__ float    g_node[(size_t)NN * 256];   // node features
__device__ float    g_h[(size_t)NN * 256];      // hidden after layer 0
__device__ float    g_wcat[2 * WROWS * 256];    // folded weights per layer
__device__ float    g_tb[2 * 4 * 3 * 32];       // folded type bias

// ---------------- helpers ---------------------------------------------------
__device__ __forceinline__ unsigned enc_f(float f) {
    unsigned b = __float_as_uint(f);
    return (b & 0x80000000u) ? ~b : (b | 0x80000000u);
}
__device__ __forceinline__ float dec_f(unsigned u) {
    return __uint_as_float((u & 0x80000000u) ? (u ^ 0x80000000u) : ~u);
}
__device__ __forceinline__ void red4(float* p, float a, float b, float c, float d) {
    asm volatile("red.global.add.v4.f32 [%0], {%1,%2,%3,%4};"
                 :: "l"(p), "f"(a), "f"(b), "f"(c), "f"(d) : "memory");
}
__device__ __forceinline__ uint32_t f2tf(float f) {
    uint32_t u;
    asm("cvt.rna.tf32.f32 %0, %1;" : "=r"(u) : "f"(f));
    return u;
}

// ---------------- weight folding --------------------------------------------
__global__ void k_prep_wcat(const float* __restrict__ w1, const float* __restrict__ wq,
                            const float* __restrict__ wv, const float* __restrict__ ec) {
    int id = blockIdx.x * blockDim.x + threadIdx.x;
    if (id >= 2 * WROWS * 256) return;
    int d = id & 255;
    int r = (id >> 8) % WROWS;
    int l = id / (WROWS * 256);
    float val;
    if (r < 128) {                       // w1 head rows (only the IN part, stride 320)
        int h = r >> 5, k = r & 31;
        val = w1[(((l * 4 + h) * 32 + k) * 320) + d];
    } else if (r < 140) {                // wqe[h,t,d] = sum_o wq[h,o,d]*ec[h,t,o]
        int rr = r - 128, h = rr / 3, t = rr % 3;
        const float* wqp = wq + ((size_t)(l * 4 + h) * 64) * 256 + d;
        const float* ecp = ec + ((l * 4 + h) * 3 + t) * 64;
        float acc = 0.f;
        #pragma unroll 8
        for (int o = 0; o < 64; o++) acc += wqp[(size_t)o * 256] * ecp[o];
        val = acc;
    } else {                             // wv rows
        int rr = r - 140, h = rr >> 6, o = rr & 63;
        val = wv[((size_t)((l * 4 + h) * 64 + o)) * 256 + d];
    }
    g_wcat[(size_t)(l * WROWS + r) * 256 + d] = val;
}

__global__ void k_prep_tb(const float* __restrict__ b1, const float* __restrict__ tq,
                          const float* __restrict__ w1) {
    int id = blockIdx.x * blockDim.x + threadIdx.x;   // id = ((l*4+h)*3+t)*32+k
    if (id >= 2 * 4 * 3 * 32) return;
    int k = id & 31;
    int rem = id >> 5;
    int t = rem % 3;
    int lh = rem / 3;                                 // l*4+h
    float acc = b1[lh * 32 + k];
    const float* tqp = tq + (lh * 3 + t) * 64;
    const float* w1p = w1 + ((size_t)(lh * 32 + k)) * 320 + 256;
    #pragma unroll 8
    for (int d = 0; d < 64; d++) acc += tqp[d] * w1p[d];
    g_tb[id] = acc;
}

// ---------------- TF32 tensor-core GEMM: P = h x Wcat^T ---------------------
// Block tile 128x64, K-chunk 32. 8 warps as 2(m) x 4(n); warp tile 64x16.
// mma.sync.aligned.m16n8k8.row.col.f32.tf32.tf32.f32
#define GBM 128
#define GBN 64
#define GBK 32
#define SKP 36   // padded K stride in smem (conflict-free: 36 mod 32 = 4)

__global__ __launch_bounds__(256) void k_gemm(const float* __restrict__ A, int layer) {
    __shared__ uint32_t As[GBM * SKP];
    __shared__ uint32_t Bs[GBN * SKP];
    const float* Bg = g_wcat + (size_t)layer * WROWS * 256;
    int tid = threadIdx.x;
    int row0 = blockIdx.y * GBM;
    int col0 = blockIdx.x * GBN;
    int warp = tid >> 5, lane = tid & 31;
    int gid = lane >> 2, tig = lane & 3;
    int wm = (warp >> 2) * 64;     // 0 or 64
    int wn = (warp & 3) * 16;      // 0,16,32,48
    int lr = tid >> 3;             // 0..31 (load row within pass)
    int lc = (tid & 7) * 4;        // 0..28 (k offset, float4)
    float acc[4][2][4] = {};

    for (int k0 = 0; k0 < 256; k0 += GBK) {
        #pragma unroll
        for (int p = 0; p < 4; p++) {
            int r = row0 + p * 32 + lr;
            float4 v = make_float4(0.f, 0.f, 0.f, 0.f);
            if (r < NN) v = *(const float4*)(A + (size_t)r * 256 + k0 + lc);
            uint32_t* d = &As[(p * 32 + lr) * SKP + lc];
            d[0] = f2tf(v.x); d[1] = f2tf(v.y); d[2] = f2tf(v.z); d[3] = f2tf(v.w);
        }
        #pragma unroll
        for (int p = 0; p < 2; p++) {
            int r = col0 + p * 32 + lr;
            float4 v = make_float4(0.f, 0.f, 0.f, 0.f);
            if (r < WROWS) v = *(const float4*)(Bg + (size_t)r * 256 + k0 + lc);
            uint32_t* d = &Bs[(p * 32 + lr) * SKP + lc];
            d[0] = f2tf(v.x); d[1] = f2tf(v.y); d[2] = f2tf(v.z); d[3] = f2tf(v.w);
        }
        __syncthreads();
        #pragma unroll
        for (int kc = 0; kc < 4; kc++) {
            int kk = kc * 8;
            uint32_t b[2][2];
            #pragma unroll
            for (int nt = 0; nt < 2; nt++) {
                int n = wn + nt * 8 + gid;
                b[nt][0] = Bs[n * SKP + kk + tig];
                b[nt][1] = Bs[n * SKP + kk + tig + 4];
            }
            #pragma unroll
            for (int mt = 0; mt < 4; mt++) {
                int m = wm + mt * 16 + gid;
                uint32_t a0 = As[m * SKP + kk + tig];
                uint32_t a1 = As[(m + 8) * SKP + kk + tig];
                uint32_t a2 = As[m * SKP + kk + tig + 4];
                uint32_t a3 = As[(m + 8) * SKP + kk + tig + 4];
                #pragma unroll
                for (int nt = 0; nt < 2; nt++) {
                    asm volatile(
                        "mma.sync.aligned.m16n8k8.row.col.f32.tf32.tf32.f32 "
                        "{%0,%1,%2,%3}, {%4,%5,%6,%7}, {%8,%9}, {%0,%1,%2,%3};"
                        : "+f"(acc[mt][nt][0]), "+f"(acc[mt][nt][1]),
                          "+f"(acc[mt][nt][2]), "+f"(acc[mt][nt][3])
                        : "r"(a0), "r"(a1), "r"(a2), "r"(a3),
                          "r"(b[nt][0]), "r"(b[nt][1]));
                }
            }
        }
        __syncthreads();
    }
    // epilogue
    #pragma unroll
    for (int mt = 0; mt < 4; mt++) {
        #pragma unroll
        for (int nt = 0; nt < 2; nt++) {
            int r = row0 + wm + mt * 16 + gid;
            int c = col0 + wn + nt * 8 + tig * 2;
            if (c < WROWS) {   // c even, WROWS even -> c+1 also valid
                if (r < NN) {
                    g_P[(size_t)r * PSTR + c]     = acc[mt][nt][0];
                    g_P[(size_t)r * PSTR + c + 1] = acc[mt][nt][1];
                }
                if (r + 8 < NN) {
                    g_P[(size_t)(r + 8) * PSTR + c]     = acc[mt][nt][2];
                    g_P[(size_t)(r + 8) * PSTR + c + 1] = acc[mt][nt][3];
                }
            }
        }
    }
}

// ---------------- per-node gate + logit table -------------------------------
__global__ __launch_bounds__(256) void k_post(const float* __restrict__ w2,
                                              const float* __restrict__ b2,
                                              const int* __restrict__ node_types,
                                              int l) {
    int warp = (blockIdx.x * blockDim.x + threadIdx.x) >> 5;
    int lane = threadIdx.x & 31;
    if (warp >= NN) return;
    int n = warp;
    int t = node_types[n];
    const float* Pr = g_P + (size_t)n * PSTR;
    float at[4];
    #pragma unroll
    for (int h = 0; h < 4; h++) {
        float hid = tanhf(Pr[h * 32 + lane] + g_tb[((l * 4 + h) * 3 + t) * 32 + lane]);
        float v = hid * w2[(l * 4 + h) * 32 + lane];
        #pragma unroll
        for (int off = 16; off; off >>= 1) v += __shfl_xor_sync(0xffffffffu, v, off);
        at[h] = 1.f / (1.f + __expf(-(v + b2[l * 4 + h])));
    }
    if (lane < 12) {
        int tt = lane >> 2, h = lane & 3;
        float q = Pr[128 + h * 3 + tt];
        float lr = q > 0.f ? q : 0.2f * q;
        g_s[n * 12 + lane] = lr * at[h];   // layout [n][t][h]
    }
}

// ---------------- segment softmax -------------------------------------------
__global__ __launch_bounds__(256) void k_b1(const int* __restrict__ ni,
                                            const int* __restrict__ ei,
                                            const int* __restrict__ etype) {
    int m = blockIdx.x * blockDim.x + threadIdx.x;
    if (m >= MM) return;
    int node = ni[m], edge = ei[m];
    int et = etype[edge];
    float4 a = *(const float4*)(g_s + node * 12 + et * 4);
    *(float4*)(g_alpha + (size_t)m * 4) = a;
    atomicMax(g_mx + edge * 4 + 0, enc_f(a.x));
    atomicMax(g_mx + edge * 4 + 1, enc_f(a.y));
    atomicMax(g_mx + edge * 4 + 2, enc_f(a.z));
    atomicMax(g_mx + edge * 4 + 3, enc_f(a.w));
}

__global__ __launch_bounds__(256) void k_b2(const int* __restrict__ ei) {
    int m = blockIdx.x * blockDim.x + threadIdx.x;
    if (m >= MM) return;
    int edge = ei[m];
    float4 a = *(const float4*)(g_alpha + (size_t)m * 4);
    float e0 = __expf(a.x - dec_f(g_mx[edge * 4 + 0]));
    float e1 = __expf(a.y - dec_f(g_mx[edge * 4 + 1]));
    float e2 = __expf(a.z - dec_f(g_mx[edge * 4 + 2]));
    float e3 = __expf(a.w - dec_f(g_mx[edge * 4 + 3]));
    *(float4*)(g_alpha + (size_t)m * 4) = make_float4(e0, e1, e2, e3);
    atomicAdd(g_den + edge * 4 + 0, e0);
    atomicAdd(g_den + edge * 4 + 1, e1);
    atomicAdd(g_den + edge * 4 + 2, e2);
    atomicAdd(g_den + edge * 4 + 3, e3);
}

// normalize: alpha <- alpha / den (done once, so b3/b4 skip the division)
__global__ __launch_bounds__(256) void k_attn(const int* __restrict__ ei) {
    int m = blockIdx.x * blockDim.x + threadIdx.x;
    if (m >= MM) return;
    int edge = ei[m];
    float4 a = *(const float4*)(g_alpha + (size_t)m * 4);
    float4 d = *(const float4*)(g_den + edge * 4);
    a.x /= d.x; a.y /= d.y; a.z /= d.z; a.w /= d.w;
    *(float4*)(g_alpha + (size_t)m * 4) = a;
}

// ---------------- scatter: node -> edge -------------------------------------
__global__ __launch_bounds__(256) void k_b3(const int* __restrict__ ni,
                                            const int* __restrict__ ei) {
    int g = blockIdx.x * blockDim.x + threadIdx.x;
    int m = g >> 5, j = g & 31;
    if (m >= MM) return;
    int node = ni[m], edge = ei[m];
    int h = j >> 3;
    float attn = g_alpha[(size_t)m * 4 + h];
    const float* Vr = g_P + (size_t)node * PSTR + VOFF + j * 8;
    float4 v0 = *(const float4*)(Vr);
    float4 v1 = *(const float4*)(Vr + 4);
    float* dst = g_edge + (size_t)edge * 256 + j * 8;
    red4(dst,     v0.x * attn, v0.y * attn, v0.z * attn, v0.w * attn);
    red4(dst + 4, v1.x * attn, v1.y * attn, v1.z * attn, v1.w * attn);
}

// ---------------- scatter: edge -> node -------------------------------------
__global__ __launch_bounds__(256) void k_b4(const int* __restrict__ ni,
                                            const int* __restrict__ ei) {
    int g = blockIdx.x * blockDim.x + threadIdx.x;
    int m = g >> 5, j = g & 31;
    if (m >= MM) return;
    int node = ni[m], edge = ei[m];
    int h = j >> 3;
    float attn = g_alpha[(size_t)m * 4 + h];
    const float* Er = g_edge + (size_t)edge * 256 + j * 8;
    float4 v0 = *(const float4*)(Er);
    float4 v1 = *(const float4*)(Er + 4);
    float* dst = g_node + (size_t)node * 256 + j * 8;
    red4(dst,     v0.x * attn, v0.y * attn, v0.z * attn, v0.w * attn);
    red4(dst + 4, v1.x * attn, v1.y * attn, v1.z * attn, v1.w * attn);
}

// ---------------- residual + LayerNorm --------------------------------------
__global__ __launch_bounds__(256) void k_ln(const float* __restrict__ hin,
                                            const float* __restrict__ g,
                                            const float* __restrict__ b,
                                            float* __restrict__ out) {
    int warp = (blockIdx.x * blockDim.x + threadIdx.x) >> 5;
    int lane = threadIdx.x & 31;
    if (warp >= NN) return;
    size_t base = (size_t)warp * 256;
    float v[8];
    float sum = 0.f;
    #pragma unroll
    for (int i = 0; i < 8; i++) {
        int c = i * 32 + lane;
        v[i] = hin[base + c] + g_node[base + c];
        sum += v[i];
    }
    #pragma unroll
    for (int off = 16; off; off >>= 1) sum += __shfl_xor_sync(0xffffffffu, sum, off);
    float mu = sum * (1.f / 256.f);
    float s2 = 0.f;
    #pragma unroll
    for (int i = 0; i < 8; i++) { float d = v[i] - mu; s2 += d * d; }
    #pragma unroll
    for (int off = 16; off; off >>= 1) s2 += __shfl_xor_sync(0xffffffffu, s2, off);
    float rstd = rsqrtf(s2 * (1.f / 256.f) + 1e-5f);
    #pragma unroll
    for (int i = 0; i < 8; i++) {
        int c = i * 32 + lane;
        out[base + c] = (v[i] - mu) * rstd * g[c] + b[c];
    }
}

// ---------------- host ------------------------------------------------------
extern "C" void kernel_launch(void* const* d_in, const int* in_sizes, int n_in,
                              void* d_out, int out_size) {
    const float* x         = (const float*)d_in[0];
    const int*   node_types= (const int*)  d_in[1];
    const int*   edge_type = (const int*)  d_in[2];
    const int*   node_idx  = (const int*)  d_in[3];
    const int*   edge_idx  = (const int*)  d_in[4];
    const float* tq        = (const float*)d_in[5];
    const float* w1        = (const float*)d_in[6];
    const float* b1        = (const float*)d_in[7];
    const float* w2        = (const float*)d_in[8];
    const float* b2        = (const float*)d_in[9];
    const float* wq        = (const float*)d_in[10];
    const float* wv        = (const float*)d_in[11];
    const float* ec        = (const float*)d_in[12];
    const float* ln_g      = (const float*)d_in[13];
    const float* ln_b      = (const float*)d_in[14];
    float* out = (float*)d_out;

    void *pmx, *pden, *pedge, *pnode, *ph;
    cudaGetSymbolAddress(&pmx,   g_mx);
    cudaGetSymbolAddress(&pden,  g_den);
    cudaGetSymbolAddress(&pedge, g_edge);
    cudaGetSymbolAddress(&pnode, g_node);
    cudaGetSymbolAddress(&ph,    g_h);
    const float* hbuf = (const float*)ph;

    k_prep_wcat<<<(2 * WROWS * 256 + 255) / 256, 256>>>(w1, wq, wv, ec);
    k_prep_tb<<<3, 256>>>(b1, tq, w1);

    for (int l = 0; l < 2; l++) {
        cudaMemsetAsync(pmx,   0, (size_t)EE * 4 * 4);
        cudaMemsetAsync(pden,  0, (size_t)EE * 4 * 4);
        cudaMemsetAsync(pedge, 0, (size_t)EE * 256 * 4);
        cudaMemsetAsync(pnode, 0, (size_t)NN * 256 * 4);

        const float* hin = l ? hbuf : x;
        dim3 gg((WROWS + GBN - 1) / GBN, (NN + GBM - 1) / GBM);
        k_gemm<<<gg, 256>>>(hin, l);
        k_post<<<(NN + 7) / 8, 256>>>(w2, b2, node_types, l);
        k_b1<<<(MM + 255) / 256, 256>>>(node_idx, edge_idx, edge_type);
        k_b2<<<(MM + 255) / 256, 256>>>(edge_idx);
        k_attn<<<(MM + 255) / 256, 256>>>(edge_idx);
        k_b3<<<(MM * 32) / 256, 256>>>(node_idx, edge_idx);
        k_b4<<<(MM * 32) / 256, 256>>>(node_idx, edge_idx);
        k_ln<<<(NN + 7) / 8, 256>>>(hin, ln_g + l * 256, ln_b + l * 256,
                                    l ? out : (float*)ph);
    }
}

// round 3
// speedup vs baseline: 1.6201x; 1.0209x over previous
#include <cuda_runtime.h>
#include <math.h>
#include <stdint.h>

#define NN 50000
#define EE 20000
#define MM 320000
#define WROWS 396   // 128 (gate MLP) + 12 (wqe) + 256 (V)
#define PSTR 400    // padded row stride of P
#define VOFF 140    // V columns start at 140 in P

// ---------------- scratch (device globals) ----------------------------------
__device__ float    g_P[(size_t)NN * PSTR];
__device__ float    g_s[NN * 12];
__device__ float    g_alpha[MM * 4];            // ex -> attn per pair
__device__ float    g_edge[(size_t)EE * 256];
__device__ float    g_h[(size_t)NN * 256];
__device__ float    g_wcat[2 * WROWS * 256];
__device__ float    g_tb[2 * 4 * 3 * 32];
// CSR scratch
__device__ int g_edeg[EE], g_eoff[EE + 1], g_ecur[EE], g_elist[MM];
__device__ int g_ndeg[NN], g_noff[NN + 1], g_ncur[NN], g_nlist[MM];

// ---------------- helpers ---------------------------------------------------
__device__ __forceinline__ uint32_t f2tf(float f) {
    uint32_t u;
    asm("cvt.rna.tf32.f32 %0, %1;" : "=r"(u) : "f"(f));
    return u;
}
__device__ __forceinline__ void cpa16(void* smem, const void* gmem, bool valid) {
    uint32_t s = (uint32_t)__cvta_generic_to_shared(smem);
    int sz = valid ? 16 : 0;
    asm volatile("cp.async.ca.shared.global [%0], [%1], 16, %2;"
                 :: "r"(s), "l"(gmem), "r"(sz));
}

// ---------------- weight folding --------------------------------------------
__global__ void k_prep_wcat(const float* __restrict__ w1, const float* __restrict__ wq,
                            const float* __restrict__ wv, const float* __restrict__ ec) {
    int id = blockIdx.x * blockDim.x + threadIdx.x;
    if (id >= 2 * WROWS * 256) return;
    int d = id & 255;
    int r = (id >> 8) % WROWS;
    int l = id / (WROWS * 256);
    float val;
    if (r < 128) {
        int h = r >> 5, k = r & 31;
        val = w1[(((l * 4 + h) * 32 + k) * 320) + d];
    } else if (r < 140) {
        int rr = r - 128, h = rr / 3, t = rr % 3;
        const float* wqp = wq + ((size_t)(l * 4 + h) * 64) * 256 + d;
        const float* ecp = ec + ((l * 4 + h) * 3 + t) * 64;
        float acc = 0.f;
        #pragma unroll 8
        for (int o = 0; o < 64; o++) acc += wqp[(size_t)o * 256] * ecp[o];
        val = acc;
    } else {
        int rr = r - 140, h = rr >> 6, o = rr & 63;
        val = wv[((size_t)((l * 4 + h) * 64 + o)) * 256 + d];
    }
    // pre-round B to tf32 so the mma sees defined operands
    g_wcat[(size_t)(l * WROWS + r) * 256 + d] = __uint_as_float(f2tf(val));
}

__global__ void k_prep_tb(const float* __restrict__ b1, const float* __restrict__ tq,
                          const float* __restrict__ w1) {
    int id = blockIdx.x * blockDim.x + threadIdx.x;
    if (id >= 2 * 4 * 3 * 32) return;
    int k = id & 31;
    int rem = id >> 5;
    int t = rem % 3;
    int lh = rem / 3;
    float acc = b1[lh * 32 + k];
    const float* tqp = tq + (lh * 3 + t) * 64;
    const float* w1p = w1 + ((size_t)(lh * 32 + k)) * 320 + 256;
    #pragma unroll 8
    for (int d = 0; d < 64; d++) acc += tqp[d] * w1p[d];
    g_tb[id] = acc;
}

// ---------------- CSR construction ------------------------------------------
__global__ void k_deg(const int* __restrict__ ni, const int* __restrict__ ei) {
    int m = blockIdx.x * blockDim.x + threadIdx.x;
    if (m >= MM) return;
    atomicAdd(&g_edeg[ei[m]], 1);
    atomicAdd(&g_ndeg[ni[m]], 1);
}

__global__ void k_scan(const int* __restrict__ deg, int* __restrict__ off, int n) {
    __shared__ int ws[32];
    __shared__ int carry;
    int tid = threadIdx.x;
    int lane = tid & 31, wid = tid >> 5;
    if (tid == 0) carry = 0;
    __syncthreads();
    for (int base = 0; base < n; base += 1024) {
        int i = base + tid;
        int v = (i < n) ? deg[i] : 0;
        int s = v;
        #pragma unroll
        for (int o = 1; o < 32; o <<= 1) {
            int t = __shfl_up_sync(0xffffffffu, s, o);
            if (lane >= o) s += t;
        }
        if (lane == 31) ws[wid] = s;
        __syncthreads();
        if (wid == 0) {
            int t = ws[lane];
            #pragma unroll
            for (int o = 1; o < 32; o <<= 1) {
                int u = __shfl_up_sync(0xffffffffu, t, o);
                if (lane >= o) t += u;
            }
            ws[lane] = t;
        }
        __syncthreads();
        int excl = s - v + (wid ? ws[wid - 1] : 0) + carry;
        if (i < n) off[i] = excl;
        if (i == n - 1) off[n] = excl + v;
        __syncthreads();
        if (tid == 0) carry += ws[31];
        __syncthreads();
    }
}

__global__ void k_fill(const int* __restrict__ ni, const int* __restrict__ ei) {
    int m = blockIdx.x * blockDim.x + threadIdx.x;
    if (m >= MM) return;
    int e = ei[m];
    int p = atomicAdd(&g_ecur[e], 1);
    g_elist[g_eoff[e] + p] = m;
    int n = ni[m];
    int q = atomicAdd(&g_ncur[n], 1);
    g_nlist[g_noff[n] + q] = m;
}

// ---------------- TF32 GEMM: P = h x Wcat^T, cp.async double-buffered -------
// Block 256x64, 8 warps as 4(m) x 2(n), warp tile 64x32.
#define GBM 256
#define GBN 64
#define GBK 32
#define SKP 36
#define SMEM_A (GBM * SKP)          // uint32 words per stage
#define SMEM_B (GBN * SKP)
#define GEMM_SMEM_BYTES ((2 * SMEM_A + 2 * SMEM_B) * 4)

__global__ __launch_bounds__(256) void k_gemm(const float* __restrict__ A, int layer) {
    extern __shared__ uint32_t sm[];
    uint32_t* As = sm;                      // [2][GBM*SKP]
    uint32_t* Bs = sm + 2 * SMEM_A;         // [2][GBN*SKP]
    const float* Bg = g_wcat + (size_t)layer * WROWS * 256;
    int tid = threadIdx.x;
    int row0 = blockIdx.y * GBM;
    int col0 = blockIdx.x * GBN;
    int warp = tid >> 5, lane = tid & 31;
    int gid = lane >> 2, tig = lane & 3;
    int wm = (warp >> 1) * 64;
    int wn = (warp & 1) * 32;
    int lr = tid >> 3;
    int lc = (tid & 7) * 4;
    float acc[4][4][4] = {};

    auto load_stage = [&](int s, int k0) {
        uint32_t* Ad = As + s * SMEM_A;
        uint32_t* Bd = Bs + s * SMEM_B;
        #pragma unroll
        for (int p = 0; p < 8; p++) {
            int r = row0 + p * 32 + lr;
            cpa16(&Ad[(p * 32 + lr) * SKP + lc], A + (size_t)r * 256 + k0 + lc, r < NN);
        }
        #pragma unroll
        for (int p = 0; p < 2; p++) {
            int r = col0 + p * 32 + lr;
            cpa16(&Bd[(p * 32 + lr) * SKP + lc], Bg + (size_t)r * 256 + k0 + lc, r < WROWS);
        }
    };

    load_stage(0, 0);
    asm volatile("cp.async.commit_group;");
    int buf = 0;
    for (int it = 0; it < 8; it++) {
        asm volatile("cp.async.wait_group 0;");
        __syncthreads();
        if (it < 7) {
            load_stage(buf ^ 1, (it + 1) * GBK);
            asm volatile("cp.async.commit_group;");
        }
        uint32_t* Ab = As + buf * SMEM_A;
        uint32_t* Bb = Bs + buf * SMEM_B;
        #pragma unroll
        for (int kc = 0; kc < 4; kc++) {
            int kk = kc * 8;
            uint32_t b[4][2];
            #pragma unroll
            for (int nt = 0; nt < 4; nt++) {
                int n = wn + nt * 8 + gid;
                b[nt][0] = Bb[n * SKP + kk + tig];
                b[nt][1] = Bb[n * SKP + kk + tig + 4];
            }
            #pragma unroll
            for (int mt = 0; mt < 4; mt++) {
                int m = wm + mt * 16 + gid;
                uint32_t a0 = f2tf(__uint_as_float(Ab[m * SKP + kk + tig]));
                uint32_t a1 = f2tf(__uint_as_float(Ab[(m + 8) * SKP + kk + tig]));
                uint32_t a2 = f2tf(__uint_as_float(Ab[m * SKP + kk + tig + 4]));
                uint32_t a3 = f2tf(__uint_as_float(Ab[(m + 8) * SKP + kk + tig + 4]));
                #pragma unroll
                for (int nt = 0; nt < 4; nt++) {
                    asm volatile(
                        "mma.sync.aligned.m16n8k8.row.col.f32.tf32.tf32.f32 "
                        "{%0,%1,%2,%3}, {%4,%5,%6,%7}, {%8,%9}, {%0,%1,%2,%3};"
                        : "+f"(acc[mt][nt][0]), "+f"(acc[mt][nt][1]),
                          "+f"(acc[mt][nt][2]), "+f"(acc[mt][nt][3])
                        : "r"(a0), "r"(a1), "r"(a2), "r"(a3),
                          "r"(b[nt][0]), "r"(b[nt][1]));
                }
            }
        }
        buf ^= 1;
    }
    #pragma unroll
    for (int mt = 0; mt < 4; mt++) {
        #pragma unroll
        for (int nt = 0; nt < 4; nt++) {
            int r = row0 + wm + mt * 16 + gid;
            int c = col0 + wn + nt * 8 + tig * 2;
            if (c < WROWS) {
                if (r < NN) {
                    g_P[(size_t)r * PSTR + c]     = acc[mt][nt][0];
                    g_P[(size_t)r * PSTR + c + 1] = acc[mt][nt][1];
                }
                if (r + 8 < NN) {
                    g_P[(size_t)(r + 8) * PSTR + c]     = acc[mt][nt][2];
                    g_P[(size_t)(r + 8) * PSTR + c + 1] = acc[mt][nt][3];
                }
            }
        }
    }
}

// ---------------- per-node gate + logit table -------------------------------
__global__ __launch_bounds__(256) void k_post(const float* __restrict__ w2,
                                              const float* __restrict__ b2,
                                              const int* __restrict__ node_types,
                                              int l) {
    int warp = (blockIdx.x * blockDim.x + threadIdx.x) >> 5;
    int lane = threadIdx.x & 31;
    if (warp >= NN) return;
    int n = warp;
    int t = node_types[n];
    const float* Pr = g_P + (size_t)n * PSTR;
    float at[4];
    #pragma unroll
    for (int h = 0; h < 4; h++) {
        float hid = tanhf(Pr[h * 32 + lane] + g_tb[((l * 4 + h) * 3 + t) * 32 + lane]);
        float v = hid * w2[(l * 4 + h) * 32 + lane];
        #pragma unroll
        for (int off = 16; off; off >>= 1) v += __shfl_xor_sync(0xffffffffu, v, off);
        at[h] = 1.f / (1.f + __expf(-(v + b2[l * 4 + h])));
    }
    if (lane < 12) {
        int tt = lane >> 2, h = lane & 3;
        float q = Pr[128 + h * 3 + tt];
        float lr = q > 0.f ? q : 0.2f * q;
        g_s[n * 12 + lane] = lr * at[h];   // [n][t][h]
    }
}

// ---------------- warp-per-edge segment softmax (no atomics) ----------------
__global__ __launch_bounds__(256) void k_soft(const int* __restrict__ ni,
                                              const int* __restrict__ etype) {
    int w = (blockIdx.x * blockDim.x + threadIdx.x) >> 5;
    int lane = threadIdx.x & 31;
    if (w >= EE) return;
    int e = w;
    int beg = g_eoff[e], deg = g_eoff[e + 1] - beg;
    if (deg == 0) return;
    int et = etype[e];
    int pi = lane >> 2, h = lane & 3;
    float mx = -INFINITY;
    for (int i0 = 0; i0 < deg; i0 += 8) {
        int i = i0 + pi;
        if (i < deg) {
            int m = g_elist[beg + i];
            float a = g_s[ni[m] * 12 + et * 4 + h];
            mx = fmaxf(mx, a);
        }
    }
    #pragma unroll
    for (int o = 4; o < 32; o <<= 1) mx = fmaxf(mx, __shfl_xor_sync(0xffffffffu, mx, o));
    float den = 0.f;
    for (int i0 = 0; i0 < deg; i0 += 8) {
        int i = i0 + pi;
        if (i < deg) {
            int m = g_elist[beg + i];
            float a = g_s[ni[m] * 12 + et * 4 + h];
            float ex = __expf(a - mx);
            g_alpha[(size_t)m * 4 + h] = ex;
            den += ex;
        }
    }
    #pragma unroll
    for (int o = 4; o < 32; o <<= 1) den += __shfl_xor_sync(0xffffffffu, den, o);
    float inv = 1.f / den;
    for (int i0 = 0; i0 < deg; i0 += 8) {
        int i = i0 + pi;
        if (i < deg) {
            int m = g_elist[beg + i];
            g_alpha[(size_t)m * 4 + h] *= inv;
        }
    }
}

// ---------------- block-per-edge gather (no atomics) ------------------------
__global__ __launch_bounds__(256) void k_edge(const int* __restrict__ ni) {
    int e = blockIdx.x;
    int j = threadIdx.x, h = j >> 6;
    __shared__ int s_m[128];
    __shared__ int s_node[128];
    __shared__ float s_a[128 * 4];
    int beg = g_eoff[e], end = g_eoff[e + 1];
    float acc = 0.f;
    for (int c0 = beg; c0 < end; c0 += 128) {
        int cnt = min(128, end - c0);
        if (j < cnt) s_m[j] = g_elist[c0 + j];
        __syncthreads();
        if (j < cnt) s_node[j] = ni[s_m[j]];
        for (int i = j; i < cnt * 4; i += 256)
            s_a[i] = g_alpha[(size_t)s_m[i >> 2] * 4 + (i & 3)];
        __syncthreads();
        #pragma unroll 4
        for (int i = 0; i < cnt; i++)
            acc += s_a[i * 4 + h] * g_P[(size_t)s_node[i] * PSTR + VOFF + j];
        __syncthreads();
    }
    g_edge[(size_t)e * 256 + j] = acc;
}

// ---------------- block-per-node gather + residual + LayerNorm --------------
__global__ __launch_bounds__(256) void k_node_ln(const int* __restrict__ ei,
                                                 const float* __restrict__ hin,
                                                 const float* __restrict__ gma,
                                                 const float* __restrict__ bet,
                                                 float* __restrict__ out) {
    int n = blockIdx.x;
    int j = threadIdx.x, h = j >> 6;
    __shared__ int s_m[64];
    __shared__ int s_e[64];
    __shared__ float s_a[64 * 4];
    __shared__ float red[8];
    int beg = g_noff[n], end = g_noff[n + 1];
    float acc = 0.f;
    for (int c0 = beg; c0 < end; c0 += 64) {
        int cnt = min(64, end - c0);
        if (j < cnt) s_m[j] = g_nlist[c0 + j];
        __syncthreads();
        if (j < cnt) s_e[j] = ei[s_m[j]];
        for (int i = j; i < cnt * 4; i += 256)
            s_a[i] = g_alpha[(size_t)s_m[i >> 2] * 4 + (i & 3)];
        __syncthreads();
        #pragma unroll 4
        for (int i = 0; i < cnt; i++)
            acc += s_a[i * 4 + h] * g_edge[(size_t)s_e[i] * 256 + j];
        __syncthreads();
    }
    float v = hin[(size_t)n * 256 + j] + acc;
    float s = v;
    #pragma unroll
    for (int o = 16; o; o >>= 1) s += __shfl_xor_sync(0xffffffffu, s, o);
    if ((j & 31) == 0) red[j >> 5] = s;
    __syncthreads();
    float mu = 0.f;
    #pragma unroll
    for (int k = 0; k < 8; k++) mu += red[k];
    mu *= (1.f / 256.f);
    __syncthreads();
    float d = v - mu;
    float s2 = d * d;
    #pragma unroll
    for (int o = 16; o; o >>= 1) s2 += __shfl_xor_sync(0xffffffffu, s2, o);
    if ((j & 31) == 0) red[j >> 5] = s2;
    __syncthreads();
    float var = 0.f;
    #pragma unroll
    for (int k = 0; k < 8; k++) var += red[k];
    float rstd = rsqrtf(var * (1.f / 256.f) + 1e-5f);
    out[(size_t)n * 256 + j] = d * rstd * gma[j] + bet[j];
}

// ---------------- host ------------------------------------------------------
extern "C" void kernel_launch(void* const* d_in, const int* in_sizes, int n_in,
                              void* d_out, int out_size) {
    const float* x         = (const float*)d_in[0];
    const int*   node_types= (const int*)  d_in[1];
    const int*   edge_type = (const int*)  d_in[2];
    const int*   node_idx  = (const int*)  d_in[3];
    const int*   edge_idx  = (const int*)  d_in[4];
    const float* tq        = (const float*)d_in[5];
    const float* w1        = (const float*)d_in[6];
    const float* b1        = (const float*)d_in[7];
    const float* w2        = (const float*)d_in[8];
    const float* b2        = (const float*)d_in[9];
    const float* wq        = (const float*)d_in[10];
    const float* wv        = (const float*)d_in[11];
    const float* ec        = (const float*)d_in[12];
    const float* ln_g      = (const float*)d_in[13];
    const float* ln_b      = (const float*)d_in[14];
    float* out = (float*)d_out;

    static bool attr_set = false;
    if (!attr_set) {
        cudaFuncSetAttribute(k_gemm, cudaFuncAttributeMaxDynamicSharedMemorySize,
                             GEMM_SMEM_BYTES);
        attr_set = true;
    }

    void *pedeg, *pndeg, *pecur, *pncur, *peoff, *pnoff, *ph;
    cudaGetSymbolAddress(&pedeg, g_edeg);
    cudaGetSymbolAddress(&pndeg, g_ndeg);
    cudaGetSymbolAddress(&pecur, g_ecur);
    cudaGetSymbolAddress(&pncur, g_ncur);
    cudaGetSymbolAddress(&peoff, g_eoff);
    cudaGetSymbolAddress(&pnoff, g_noff);
    cudaGetSymbolAddress(&ph,    g_h);
    const float* hbuf = (const float*)ph;

    cudaMemsetAsync(pedeg, 0, EE * 4);
    cudaMemsetAsync(pndeg, 0, NN * 4);
    cudaMemsetAsync(pecur, 0, EE * 4);
    cudaMemsetAsync(pncur, 0, NN * 4);

    k_deg<<<MM / 256, 256>>>(node_idx, edge_idx);
    k_scan<<<1, 1024>>>((const int*)pedeg, (int*)peoff, EE);
    k_scan<<<1, 1024>>>((const int*)pndeg, (int*)pnoff, NN);
    k_fill<<<MM / 256, 256>>>(node_idx, edge_idx);

    k_prep_wcat<<<(2 * WROWS * 256 + 255) / 256, 256>>>(w1, wq, wv, ec);
    k_prep_tb<<<3, 256>>>(b1, tq, w1);

    for (int l = 0; l < 2; l++) {
        const float* hin = l ? hbuf : x;
        dim3 gg((WROWS + GBN - 1) / GBN, (NN + GBM - 1) / GBM);
        k_gemm<<<gg, 256, GEMM_SMEM_BYTES>>>(hin, l);
        k_post<<<(NN + 7) / 8, 256>>>(w2, b2, node_types, l);
        k_soft<<<(EE + 7) / 8, 256>>>(node_idx, edge_type);
        k_edge<<<EE, 256>>>(node_idx);
        k_node_ln<<<NN, 256>>>(edge_idx, hin, ln_g + l * 256, ln_b + l * 256,
                               l ? out : (float*)ph);
    }
}

// round 6
// speedup vs baseline: 1.8795x; 1.1602x over previous
#include <cuda_runtime.h>
#include <cuda_bf16.h>
#include <math.h>
#include <stdint.h>

#define NN 50000
#define EE 20000
#define MM 320000
#define WROWS 396   // 128 (gate MLP) + 12 (wqe) + 256 (V)
#define PSTR 400    // padded row stride of P
#define VOFF 140    // V columns start at 140 in P

// ---------------- scratch (device globals) ----------------------------------
__device__ float          g_P[(size_t)NN * PSTR];
__device__ float          g_s[NN * 12];
__device__ float          g_alpha[MM * 4];
__device__ float          g_edge[(size_t)EE * 256];
__device__ float          g_h[(size_t)NN * 256];        // fp32 hidden (residual)
__device__ __nv_bfloat16  g_hb[(size_t)NN * 256];       // bf16 mirror for GEMM
__device__ __nv_bfloat16  g_wcatb[2 * WROWS * 256];     // folded weights (bf16)
__device__ float          g_tb[2 * 4 * 3 * 32];
// CSR scratch
__device__ int g_edeg[EE], g_eoff[EE + 1], g_ecur[EE], g_elist[MM], g_epart[64];
__device__ int g_ndeg[NN], g_noff[NN + 1], g_ncur[NN], g_nlist[MM], g_npart[64];

// ---------------- helpers ---------------------------------------------------
__device__ __forceinline__ void cpa16(void* smem, const void* gmem, bool valid) {
    uint32_t s = (uint32_t)__cvta_generic_to_shared(smem);
    int sz = valid ? 16 : 0;
    asm volatile("cp.async.ca.shared.global [%0], [%1], 16, %2;"
                 :: "r"(s), "l"(gmem), "r"(sz));
}

// ---------------- input conversion ------------------------------------------
__global__ void k_cvt(const float* __restrict__ x) {
    int id = blockIdx.x * blockDim.x + threadIdx.x;
    if (id >= NN * 64) return;
    float4 v = *(const float4*)(x + (size_t)id * 4);
    __nv_bfloat16* d = g_hb + (size_t)id * 4;
    d[0] = __float2bfloat16(v.x); d[1] = __float2bfloat16(v.y);
    d[2] = __float2bfloat16(v.z); d[3] = __float2bfloat16(v.w);
}

// ---------------- weight folding --------------------------------------------
__global__ void k_prep_wcat(const float* __restrict__ w1, const float* __restrict__ wq,
                            const float* __restrict__ wv, const float* __restrict__ ec) {
    int id = blockIdx.x * blockDim.x + threadIdx.x;
    if (id >= 2 * WROWS * 256) return;
    int d = id & 255;
    int r = (id >> 8) % WROWS;
    int l = id / (WROWS * 256);
    float val;
    if (r < 128) {
        int h = r >> 5, k = r & 31;
        val = w1[(((l * 4 + h) * 32 + k) * 320) + d];
    } else if (r < 140) {
        int rr = r - 128, h = rr / 3, t = rr % 3;
        const float* wqp = wq + ((size_t)(l * 4 + h) * 64) * 256 + d;
        const float* ecp = ec + ((l * 4 + h) * 3 + t) * 64;
        float acc = 0.f;
        #pragma unroll 8
        for (int o = 0; o < 64; o++) acc += wqp[(size_t)o * 256] * ecp[o];
        val = acc;
    } else {
        int rr = r - 140, h = rr >> 6, o = rr & 63;
        val = wv[((size_t)((l * 4 + h) * 64 + o)) * 256 + d];
    }
    g_wcatb[(size_t)(l * WROWS + r) * 256 + d] = __float2bfloat16(val);
}

__global__ void k_prep_tb(const float* __restrict__ b1, const float* __restrict__ tq,
                          const float* __restrict__ w1) {
    int id = blockIdx.x * blockDim.x + threadIdx.x;
    if (id >= 2 * 4 * 3 * 32) return;
    int k = id & 31;
    int rem = id >> 5;
    int t = rem % 3;
    int lh = rem / 3;
    float acc = b1[lh * 32 + k];
    const float* tqp = tq + (lh * 3 + t) * 64;
    const float* w1p = w1 + ((size_t)(lh * 32 + k)) * 320 + 256;
    #pragma unroll 8
    for (int d = 0; d < 64; d++) acc += tqp[d] * w1p[d];
    g_tb[id] = acc;
}

// ---------------- CSR construction ------------------------------------------
__global__ void k_deg(const int* __restrict__ ni, const int* __restrict__ ei) {
    int m = blockIdx.x * blockDim.x + threadIdx.x;
    if (m >= MM) return;
    atomicAdd(&g_edeg[ei[m]], 1);
    atomicAdd(&g_ndeg[ni[m]], 1);
}

// multi-block exclusive scan, step 1: per-block scan + block total
__global__ __launch_bounds__(1024) void k_scan1(const int* __restrict__ deg,
                                                int* __restrict__ out,
                                                int* __restrict__ part, int n) {
    __shared__ int ws[32];
    int tid = threadIdx.x, lane = tid & 31, wid = tid >> 5;
    int i = blockIdx.x * 1024 + tid;
    int v = (i < n) ? deg[i] : 0;
    int s = v;
    #pragma unroll
    for (int o = 1; o < 32; o <<= 1) {
        int t = __shfl_up_sync(0xffffffffu, s, o);
        if (lane >= o) s += t;
    }
    if (lane == 31) ws[wid] = s;
    __syncthreads();
    if (wid == 0) {
        int t = ws[lane];
        #pragma unroll
        for (int o = 1; o < 32; o <<= 1) {
            int u = __shfl_up_sync(0xffffffffu, t, o);
            if (lane >= o) t += u;
        }
        ws[lane] = t;
    }
    __syncthreads();
    int incl = s + (wid ? ws[wid - 1] : 0);
    if (i < n) out[i] = incl - v;
    if (tid == 1023) part[blockIdx.x] = incl;
}

// step 2: exclusive scan of partials (nb <= 64, serial on one thread)
__global__ void k_scan2(int* part, int nb) {
    if (threadIdx.x != 0) return;
    int acc = 0;
    for (int b = 0; b < nb; b++) {
        int v = part[b];
        part[b] = acc;
        acc += v;
    }
    part[nb] = acc;
}

// step 3: add partial offsets, write total at off[n]
__global__ __launch_bounds__(1024) void k_scan3(int* __restrict__ off,
                                                const int* __restrict__ part,
                                                int n, int nb) {
    int i = blockIdx.x * 1024 + threadIdx.x;
    if (i < n) off[i] += part[i >> 10];
    if (i == 0) off[n] = part[nb];
}

__global__ void k_fill(const int* __restrict__ ni, const int* __restrict__ ei) {
    int m = blockIdx.x * blockDim.x + threadIdx.x;
    if (m >= MM) return;
    int e = ei[m];
    int p = atomicAdd(&g_ecur[e], 1);
    g_elist[g_eoff[e] + p] = m;
    int n = ni[m];
    int q = atomicAdd(&g_ncur[n], 1);
    g_nlist[g_noff[n] + q] = m;
}

// ---------------- bf16 GEMM: P = h x Wcat^T ---------------------------------
// Block 256x64, K-chunk 64 (bf16). 8 warps as 4(m) x 2(n); warp tile 64x32.
// mma.sync.aligned.m16n8k16.row.col.f32.bf16.bf16.f32, cp.async double-buffer.
#define GBM 256
#define GBN 64
#define GBK 64
#define SKPB 72                       // bf16 units per row stride (conflict-free)
#define SMA (GBM * SKPB)              // bf16 units per A stage
#define SMB (GBN * SKPB)
#define GEMM_SMEM_BYTES ((2 * SMA + 2 * SMB) * 2)

__global__ __launch_bounds__(256) void k_gemm(const __nv_bfloat16* __restrict__ A,
                                              int layer) {
    extern __shared__ __nv_bfloat16 smb[];
    __nv_bfloat16* As = smb;
    __nv_bfloat16* Bs = smb + 2 * SMA;
    const __nv_bfloat16* Bg = g_wcatb + (size_t)layer * WROWS * 256;
    int tid = threadIdx.x;
    int row0 = blockIdx.y * GBM;
    int col0 = blockIdx.x * GBN;
    int warp = tid >> 5, lane = tid & 31;
    int gid = lane >> 2, tig = lane & 3;
    int wm = (warp >> 1) * 64;
    int wn = (warp & 1) * 32;
    int lr = tid >> 3;                 // 0..31
    int lcb = (tid & 7) * 8;           // bf16 offset (16B granules)
    float acc[4][4][4] = {};

    auto load_stage = [&](int s, int k0) {
        __nv_bfloat16* Ad = As + s * SMA;
        __nv_bfloat16* Bd = Bs + s * SMB;
        #pragma unroll
        for (int p = 0; p < 8; p++) {
            int r = row0 + p * 32 + lr;
            cpa16(&Ad[(p * 32 + lr) * SKPB + lcb], A + (size_t)r * 256 + k0 + lcb, r < NN);
        }
        #pragma unroll
        for (int p = 0; p < 2; p++) {
            int r = col0 + p * 32 + lr;
            cpa16(&Bd[(p * 32 + lr) * SKPB + lcb], Bg + (size_t)r * 256 + k0 + lcb, r < WROWS);
        }
    };

    load_stage(0, 0);
    asm volatile("cp.async.commit_group;");
    int buf = 0;
    #pragma unroll 1
    for (int it = 0; it < 4; it++) {          // 256 / 64
        asm volatile("cp.async.wait_group 0;");
        __syncthreads();
        if (it < 3) {
            load_stage(buf ^ 1, (it + 1) * GBK);
            asm volatile("cp.async.commit_group;");
        }
        const __nv_bfloat16* Ab = As + buf * SMA;
        const __nv_bfloat16* Bb = Bs + buf * SMB;
        #pragma unroll
        for (int kc = 0; kc < 4; kc++) {      // k-steps of 16
            int kk = kc * 16;
            uint32_t b[4][2];
            #pragma unroll
            for (int nt = 0; nt < 4; nt++) {
                int n = wn + nt * 8 + gid;
                b[nt][0] = *(const uint32_t*)&Bb[n * SKPB + kk + 2 * tig];
                b[nt][1] = *(const uint32_t*)&Bb[n * SKPB + kk + 2 * tig + 8];
            }
            #pragma unroll
            for (int mt = 0; mt < 4; mt++) {
                int m = wm + mt * 16 + gid;
                uint32_t a0 = *(const uint32_t*)&Ab[m * SKPB + kk + 2 * tig];
                uint32_t a1 = *(const uint32_t*)&Ab[(m + 8) * SKPB + kk + 2 * tig];
                uint32_t a2 = *(const uint32_t*)&Ab[m * SKPB + kk + 2 * tig + 8];
                uint32_t a3 = *(const uint32_t*)&Ab[(m + 8) * SKPB + kk + 2 * tig + 8];
                #pragma unroll
                for (int nt = 0; nt < 4; nt++) {
                    asm volatile(
                        "mma.sync.aligned.m16n8k16.row.col.f32.bf16.bf16.f32 "
                        "{%0,%1,%2,%3}, {%4,%5,%6,%7}, {%8,%9}, {%0,%1,%2,%3};"
                        : "+f"(acc[mt][nt][0]), "+f"(acc[mt][nt][1]),
                          "+f"(acc[mt][nt][2]), "+f"(acc[mt][nt][3])
                        : "r"(a0), "r"(a1), "r"(a2), "r"(a3),
                          "r"(b[nt][0]), "r"(b[nt][1]));
                }
            }
        }
        buf ^= 1;
    }
    #pragma unroll
    for (int mt = 0; mt < 4; mt++) {
        #pragma unroll
        for (int nt = 0; nt < 4; nt++) {
            int r = row0 + wm + mt * 16 + gid;
            int c = col0 + wn + nt * 8 + tig * 2;
            if (c < WROWS) {
                if (r < NN) {
                    g_P[(size_t)r * PSTR + c]     = acc[mt][nt][0];
                    g_P[(size_t)r * PSTR + c + 1] = acc[mt][nt][1];
                }
                if (r + 8 < NN) {
                    g_P[(size_t)(r + 8) * PSTR + c]     = acc[mt][nt][2];
                    g_P[(size_t)(r + 8) * PSTR + c + 1] = acc[mt][nt][3];
                }
            }
        }
    }
}

// ---------------- per-node gate + logit table -------------------------------
__global__ __launch_bounds__(256) void k_post(const float* __restrict__ w2,
                                              const float* __restrict__ b2,
                                              const int* __restrict__ node_types,
                                              int l) {
    int warp = (blockIdx.x * blockDim.x + threadIdx.x) >> 5;
    int lane = threadIdx.x & 31;
    if (warp >= NN) return;
    int n = warp;
    int t = node_types[n];
    const float* Pr = g_P + (size_t)n * PSTR;
    float at[4];
    #pragma unroll
    for (int h = 0; h < 4; h++) {
        float hid = tanhf(Pr[h * 32 + lane] + g_tb[((l * 4 + h) * 3 + t) * 32 + lane]);
        float v = hid * w2[(l * 4 + h) * 32 + lane];
        #pragma unroll
        for (int off = 16; off; off >>= 1) v += __shfl_xor_sync(0xffffffffu, v, off);
        at[h] = 1.f / (1.f + __expf(-(v + b2[l * 4 + h])));
    }
    if (lane < 12) {
        int tt = lane >> 2, h = lane & 3;
        float q = Pr[128 + h * 3 + tt];
        float lr = q > 0.f ? q : 0.2f * q;
        g_s[n * 12 + lane] = lr * at[h];   // [n][t][h]
    }
}

// ---------------- warp-per-edge segment softmax (no atomics) ----------------
__global__ __launch_bounds__(256) void k_soft(const int* __restrict__ ni,
                                              const int* __restrict__ etype) {
    int w = (blockIdx.x * blockDim.x + threadIdx.x) >> 5;
    int lane = threadIdx.x & 31;
    if (w >= EE) return;
    int e = w;
    int beg = g_eoff[e], deg = g_eoff[e + 1] - beg;
    if (deg == 0) return;
    int et = etype[e];
    int pi = lane >> 2, h = lane & 3;
    float mx = -INFINITY;
    for (int i0 = 0; i0 < deg; i0 += 8) {
        int i = i0 + pi;
        if (i < deg) {
            int m = g_elist[beg + i];
            float a = g_s[ni[m] * 12 + et * 4 + h];
            mx = fmaxf(mx, a);
        }
    }
    #pragma unroll
    for (int o = 4; o < 32; o <<= 1) mx = fmaxf(mx, __shfl_xor_sync(0xffffffffu, mx, o));
    float den = 0.f;
    for (int i0 = 0; i0 < deg; i0 += 8) {
        int i = i0 + pi;
        if (i < deg) {
            int m = g_elist[beg + i];
            float a = g_s[ni[m] * 12 + et * 4 + h];
            float ex = __expf(a - mx);
            g_alpha[(size_t)m * 4 + h] = ex;
            den += ex;
        }
    }
    #pragma unroll
    for (int o = 4; o < 32; o <<= 1) den += __shfl_xor_sync(0xffffffffu, den, o);
    float inv = 1.f / den;
    for (int i0 = 0; i0 < deg; i0 += 8) {
        int i = i0 + pi;
        if (i < deg) {
            int m = g_elist[beg + i];
            g_alpha[(size_t)m * 4 + h] *= inv;
        }
    }
}

// ---------------- block-per-edge gather (no atomics) ------------------------
__global__ __launch_bounds__(256) void k_edge(const int* __restrict__ ni) {
    int e = blockIdx.x;
    int j = threadIdx.x, h = j >> 6;
    __shared__ int s_m[128];
    __shared__ int s_node[128];
    __shared__ float s_a[128 * 4];
    int beg = g_eoff[e], end = g_eoff[e + 1];
    float acc = 0.f;
    for (int c0 = beg; c0 < end; c0 += 128) {
        int cnt = min(128, end - c0);
        if (j < cnt) s_m[j] = g_elist[c0 + j];
        __syncthreads();
        if (j < cnt) s_node[j] = ni[s_m[j]];
        for (int i = j; i < cnt * 4; i += 256)
            s_a[i] = g_alpha[(size_t)s_m[i >> 2] * 4 + (i & 3)];
        __syncthreads();
        #pragma unroll 4
        for (int i = 0; i < cnt; i++)
            acc += s_a[i * 4 + h] * g_P[(size_t)s_node[i] * PSTR + VOFF + j];
        __syncthreads();
    }
    g_edge[(size_t)e * 256 + j] = acc;
}

// ---------------- block-per-node gather + residual + LayerNorm --------------
__global__ __launch_bounds__(256) void k_node_ln(const int* __restrict__ ei,
                                                 const float* __restrict__ hin,
                                                 const float* __restrict__ gma,
                                                 const float* __restrict__ bet,
                                                 float* __restrict__ outf,
                                                 __nv_bfloat16* __restrict__ outb) {
    int n = blockIdx.x;
    int j = threadIdx.x, h = j >> 6;
    __shared__ int s_m[64];
    __shared__ int s_e[64];
    __shared__ float s_a[64 * 4];
    __shared__ float red[8];
    int beg = g_noff[n], end = g_noff[n + 1];
    float acc = 0.f;
    for (int c0 = beg; c0 < end; c0 += 64) {
        int cnt = min(64, end - c0);
        if (j < cnt) s_m[j] = g_nlist[c0 + j];
        __syncthreads();
        if (j < cnt) s_e[j] = ei[s_m[j]];
        for (int i = j; i < cnt * 4; i += 256)
            s_a[i] = g_alpha[(size_t)s_m[i >> 2] * 4 + (i & 3)];
        __syncthreads();
        #pragma unroll 4
        for (int i = 0; i < cnt; i++)
            acc += s_a[i * 4 + h] * g_edge[(size_t)s_e[i] * 256 + j];
        __syncthreads();
    }
    float v = hin[(size_t)n * 256 + j] + acc;
    float s = v;
    #pragma unroll
    for (int o = 16; o; o >>= 1) s += __shfl_xor_sync(0xffffffffu, s, o);
    if ((j & 31) == 0) red[j >> 5] = s;
    __syncthreads();
    float mu = 0.f;
    #pragma unroll
    for (int k = 0; k < 8; k++) mu += red[k];
    mu *= (1.f / 256.f);
    __syncthreads();
    float d = v - mu;
    float s2 = d * d;
    #pragma unroll
    for (int o = 16; o; o >>= 1) s2 += __shfl_xor_sync(0xffffffffu, s2, o);
    if ((j & 31) == 0) red[j >> 5] = s2;
    __syncthreads();
    float var = 0.f;
    #pragma unroll
    for (int k = 0; k < 8; k++) var += red[k];
    float rstd = rsqrtf(var * (1.f / 256.f) + 1e-5f);
    float r = d * rstd * gma[j] + bet[j];
    outf[(size_t)n * 256 + j] = r;
    if (outb) outb[(size_t)n * 256 + j] = __float2bfloat16(r);
}

// ---------------- host ------------------------------------------------------
extern "C" void kernel_launch(void* const* d_in, const int* in_sizes, int n_in,
                              void* d_out, int out_size) {
    const float* x         = (const float*)d_in[0];
    const int*   node_types= (const int*)  d_in[1];
    const int*   edge_type = (const int*)  d_in[2];
    const int*   node_idx  = (const int*)  d_in[3];
    const int*   edge_idx  = (const int*)  d_in[4];
    const float* tq        = (const float*)d_in[5];
    const float* w1        = (const float*)d_in[6];
    const float* b1        = (const float*)d_in[7];
    const float* w2        = (const float*)d_in[8];
    const float* b2        = (const float*)d_in[9];
    const float* wq        = (const float*)d_in[10];
    const float* wv        = (const float*)d_in[11];
    const float* ec        = (const float*)d_in[12];
    const float* ln_g      = (const float*)d_in[13];
    const float* ln_b      = (const float*)d_in[14];
    float* out = (float*)d_out;

    static bool attr_set = false;
    if (!attr_set) {
        cudaFuncSetAttribute(k_gemm, cudaFuncAttributeMaxDynamicSharedMemorySize,
                             GEMM_SMEM_BYTES);
        attr_set = true;
    }

    void *pedeg, *pndeg, *pecur, *pncur, *peoff, *pnoff, *pepart, *pnpart, *ph, *phb;
    cudaGetSymbolAddress(&pedeg,  g_edeg);
    cudaGetSymbolAddress(&pndeg,  g_ndeg);
    cudaGetSymbolAddress(&pecur,  g_ecur);
    cudaGetSymbolAddress(&pncur,  g_ncur);
    cudaGetSymbolAddress(&peoff,  g_eoff);
    cudaGetSymbolAddress(&pnoff,  g_noff);
    cudaGetSymbolAddress(&pepart, g_epart);
    cudaGetSymbolAddress(&pnpart, g_npart);
    cudaGetSymbolAddress(&ph,     g_h);
    cudaGetSymbolAddress(&phb,    g_hb);
    const float* hbuf = (const float*)ph;
    __nv_bfloat16* hbbuf = (__nv_bfloat16*)phb;

    cudaMemsetAsync(pedeg, 0, EE * 4);
    cudaMemsetAsync(pndeg, 0, NN * 4);
    cudaMemsetAsync(pecur, 0, EE * 4);
    cudaMemsetAsync(pncur, 0, NN * 4);

    const int NB_E = (EE + 1023) / 1024;   // 20
    const int NB_N = (NN + 1023) / 1024;   // 49
    dim3 gg((WROWS + GBN - 1) / GBN, (NN + GBM - 1) / GBM);

    // launch index 3 = first k_gemm (profiled by ncu)
    k_cvt<<<(NN * 64 + 255) / 256, 256>>>(x);
    k_prep_wcat<<<(2 * WROWS * 256 + 255) / 256, 256>>>(w1, wq, wv, ec);
    k_prep_tb<<<3, 256>>>(b1, tq, w1);

    for (int l = 0; l < 2; l++) {
        const float* hin = l ? hbuf : x;
        k_gemm<<<gg, 256, GEMM_SMEM_BYTES>>>(hbbuf, l);
        if (l == 0) {
            // CSR build overlapped into the stream after the first GEMM
            k_deg<<<MM / 256, 256>>>(node_idx, edge_idx);
            k_scan1<<<NB_E, 1024>>>((const int*)pedeg, (int*)peoff, (int*)pepart, EE);
            k_scan1<<<NB_N, 1024>>>((const int*)pndeg, (int*)pnoff, (int*)pnpart, NN);
            k_scan2<<<1, 32>>>((int*)pepart, NB_E);
            k_scan2<<<1, 32>>>((int*)pnpart, NB_N);
            k_scan3<<<NB_E, 1024>>>((int*)peoff, (const int*)pepart, EE, NB_E);
            k_scan3<<<NB_N, 1024>>>((int*)pnoff, (const int*)pnpart, NN, NB_N);
            k_fill<<<MM / 256, 256>>>(node_idx, edge_idx);
        }
        k_post<<<(NN + 7) / 8, 256>>>(w2, b2, node_types, l);
        k_soft<<<(EE + 7) / 8, 256>>>(node_idx, edge_type);
        k_edge<<<EE, 256>>>(node_idx);
        k_node_ln<<<NN, 256>>>(edge_idx, hin, ln_g + l * 256, ln_b + l * 256,
                               l ? out : (float*)ph,
                               l ? (__nv_bfloat16*)nullptr : hbbuf);
    }
}

// round 11
// speedup vs baseline: 1.9147x; 1.0187x over previous
#include <cuda_runtime.h>
#include <cuda_bf16.h>
#include <math.h>
#include <stdint.h>

#define NN 50000
#define EE 20000
#define MM 320000
#define WROWS 396   // 128 (gate MLP) + 12 (wqe) + 256 (V)
#define PSTR 400    // padded row stride of P
#define VOFF 140    // V columns start at 140 in P

// ---------------- scratch (device globals) ----------------------------------
__device__ float          g_P[(size_t)NN * PSTR];
__device__ float          g_s[NN * 12];
__device__ float          g_alpha[MM * 4];
__device__ float          g_edge[(size_t)EE * 256];
__device__ float          g_h[(size_t)NN * 256];        // fp32 hidden (residual)
__device__ __nv_bfloat16  g_hb[(size_t)NN * 256];       // bf16 mirror for GEMM
__device__ __nv_bfloat16  g_wcatb[2 * WROWS * 256];     // folded weights (bf16)
__device__ float          g_tb[2 * 4 * 3 * 32];
// CSR scratch
__device__ int g_edeg[EE], g_eoff[EE + 1], g_ecur[EE], g_elist[MM], g_epart[64];
__device__ int g_ndeg[NN], g_noff[NN + 1], g_ncur[NN], g_nlist[MM], g_npart[64];

// ---------------- helpers ---------------------------------------------------
__device__ __forceinline__ void cpa16(void* smem, const void* gmem, bool valid) {
    uint32_t s = (uint32_t)__cvta_generic_to_shared(smem);
    int sz = valid ? 16 : 0;
    asm volatile("cp.async.ca.shared.global [%0], [%1], 16, %2;"
                 :: "r"(s), "l"(gmem), "r"(sz));
}

// ---------------- input conversion ------------------------------------------
__global__ void k_cvt(const float* __restrict__ x) {
    int id = blockIdx.x * blockDim.x + threadIdx.x;
    if (id >= NN * 64) return;
    float4 v = *(const float4*)(x + (size_t)id * 4);
    __nv_bfloat16* d = g_hb + (size_t)id * 4;
    d[0] = __float2bfloat16(v.x); d[1] = __float2bfloat16(v.y);
    d[2] = __float2bfloat16(v.z); d[3] = __float2bfloat16(v.w);
}

// ---------------- weight folding --------------------------------------------
__global__ void k_prep_wcat(const float* __restrict__ w1, const float* __restrict__ wq,
                            const float* __restrict__ wv, const float* __restrict__ ec) {
    int id = blockIdx.x * blockDim.x + threadIdx.x;
    if (id >= 2 * WROWS * 256) return;
    int d = id & 255;
    int r = (id >> 8) % WROWS;
    int l = id / (WROWS * 256);
    float val;
    if (r < 128) {
        int h = r >> 5, k = r & 31;
        val = w1[(((l * 4 + h) * 32 + k) * 320) + d];
    } else if (r < 140) {
        int rr = r - 128, h = rr / 3, t = rr % 3;
        const float* wqp = wq + ((size_t)(l * 4 + h) * 64) * 256 + d;
        const float* ecp = ec + ((l * 4 + h) * 3 + t) * 64;
        float acc = 0.f;
        #pragma unroll 8
        for (int o = 0; o < 64; o++) acc += wqp[(size_t)o * 256] * ecp[o];
        val = acc;
    } else {
        int rr = r - 140, h = rr >> 6, o = rr & 63;
        val = wv[((size_t)((l * 4 + h) * 64 + o)) * 256 + d];
    }
    g_wcatb[(size_t)(l * WROWS + r) * 256 + d] = __float2bfloat16(val);
}

__global__ void k_prep_tb(const float* __restrict__ b1, const float* __restrict__ tq,
                          const float* __restrict__ w1) {
    int id = blockIdx.x * blockDim.x + threadIdx.x;
    if (id >= 2 * 4 * 3 * 32) return;
    int k = id & 31;
    int rem = id >> 5;
    int t = rem % 3;
    int lh = rem / 3;
    float acc = b1[lh * 32 + k];
    const float* tqp = tq + (lh * 3 + t) * 64;
    const float* w1p = w1 + ((size_t)(lh * 32 + k)) * 320 + 256;
    #pragma unroll 8
    for (int d = 0; d < 64; d++) acc += tqp[d] * w1p[d];
    g_tb[id] = acc;
}

// ---------------- CSR construction ------------------------------------------
__global__ void k_deg(const int* __restrict__ ni, const int* __restrict__ ei) {
    int m = blockIdx.x * blockDim.x + threadIdx.x;
    if (m >= MM) return;
    atomicAdd(&g_edeg[ei[m]], 1);
    atomicAdd(&g_ndeg[ni[m]], 1);
}

__global__ __launch_bounds__(1024) void k_scan1(const int* __restrict__ deg,
                                                int* __restrict__ out,
                                                int* __restrict__ part, int n) {
    __shared__ int ws[32];
    int tid = threadIdx.x, lane = tid & 31, wid = tid >> 5;
    int i = blockIdx.x * 1024 + tid;
    int v = (i < n) ? deg[i] : 0;
    int s = v;
    #pragma unroll
    for (int o = 1; o < 32; o <<= 1) {
        int t = __shfl_up_sync(0xffffffffu, s, o);
        if (lane >= o) s += t;
    }
    if (lane == 31) ws[wid] = s;
    __syncthreads();
    if (wid == 0) {
        int t = ws[lane];
        #pragma unroll
        for (int o = 1; o < 32; o <<= 1) {
            int u = __shfl_up_sync(0xffffffffu, t, o);
            if (lane >= o) t += u;
        }
        ws[lane] = t;
    }
    __syncthreads();
    int incl = s + (wid ? ws[wid - 1] : 0);
    if (i < n) out[i] = incl - v;
    if (tid == 1023) part[blockIdx.x] = incl;
}

__global__ void k_scan2(int* part, int nb) {
    if (threadIdx.x != 0) return;
    int acc = 0;
    for (int b = 0; b < nb; b++) {
        int v = part[b];
        part[b] = acc;
        acc += v;
    }
    part[nb] = acc;
}

__global__ __launch_bounds__(1024) void k_scan3(int* __restrict__ off,
                                                const int* __restrict__ part,
                                                int n, int nb) {
    int i = blockIdx.x * 1024 + threadIdx.x;
    if (i < n) off[i] += part[i >> 10];
    if (i == 0) off[n] = part[nb];
}

__global__ void k_fill(const int* __restrict__ ni, const int* __restrict__ ei) {
    int m = blockIdx.x * blockDim.x + threadIdx.x;
    if (m >= MM) return;
    int e = ei[m];
    int p = atomicAdd(&g_ecur[e], 1);
    g_elist[g_eoff[e] + p] = m;
    int n = ni[m];
    int q = atomicAdd(&g_ncur[n], 1);
    g_nlist[g_noff[n] + q] = m;
}

// ---------------- bf16 GEMM: P = h x Wcat^T ---------------------------------
#define GBM 256
#define GBN 64
#define GBK 64
#define SKPB 72
#define SMA (GBM * SKPB)
#define SMB (GBN * SKPB)
#define GEMM_SMEM_BYTES ((2 * SMA + 2 * SMB) * 2)

__global__ __launch_bounds__(256) void k_gemm(const __nv_bfloat16* __restrict__ A,
                                              int layer) {
    extern __shared__ __nv_bfloat16 smb[];
    __nv_bfloat16* As = smb;
    __nv_bfloat16* Bs = smb + 2 * SMA;
    const __nv_bfloat16* Bg = g_wcatb + (size_t)layer * WROWS * 256;
    int tid = threadIdx.x;
    int row0 = blockIdx.y * GBM;
    int col0 = blockIdx.x * GBN;
    int warp = tid >> 5, lane = tid & 31;
    int gid = lane >> 2, tig = lane & 3;
    int wm = (warp >> 1) * 64;
    int wn = (warp & 1) * 32;
    int lr = tid >> 3;
    int lcb = (tid & 7) * 8;
    float acc[4][4][4] = {};

    auto load_stage = [&](int s, int k0) {
        __nv_bfloat16* Ad = As + s * SMA;
        __nv_bfloat16* Bd = Bs + s * SMB;
        #pragma unroll
        for (int p = 0; p < 8; p++) {
            int r = row0 + p * 32 + lr;
            cpa16(&Ad[(p * 32 + lr) * SKPB + lcb], A + (size_t)r * 256 + k0 + lcb, r < NN);
        }
        #pragma unroll
        for (int p = 0; p < 2; p++) {
            int r = col0 + p * 32 + lr;
            cpa16(&Bd[(p * 32 + lr) * SKPB + lcb], Bg + (size_t)r * 256 + k0 + lcb, r < WROWS);
        }
    };

    load_stage(0, 0);
    asm volatile("cp.async.commit_group;");
    int buf = 0;
    #pragma unroll 1
    for (int it = 0; it < 4; it++) {
        asm volatile("cp.async.wait_group 0;");
        __syncthreads();
        if (it < 3) {
            load_stage(buf ^ 1, (it + 1) * GBK);
            asm volatile("cp.async.commit_group;");
        }
        const __nv_bfloat16* Ab = As + buf * SMA;
        const __nv_bfloat16* Bb = Bs + buf * SMB;
        #pragma unroll
        for (int kc = 0; kc < 4; kc++) {
            int kk = kc * 16;
            uint32_t b[4][2];
            #pragma unroll
            for (int nt = 0; nt < 4; nt++) {
                int n = wn + nt * 8 + gid;
                b[nt][0] = *(const uint32_t*)&Bb[n * SKPB + kk + 2 * tig];
                b[nt][1] = *(const uint32_t*)&Bb[n * SKPB + kk + 2 * tig + 8];
            }
            #pragma unroll
            for (int mt = 0; mt < 4; mt++) {
                int m = wm + mt * 16 + gid;
                uint32_t a0 = *(const uint32_t*)&Ab[m * SKPB + kk + 2 * tig];
                uint32_t a1 = *(const uint32_t*)&Ab[(m + 8) * SKPB + kk + 2 * tig];
                uint32_t a2 = *(const uint32_t*)&Ab[m * SKPB + kk + 2 * tig + 8];
                uint32_t a3 = *(const uint32_t*)&Ab[(m + 8) * SKPB + kk + 2 * tig + 8];
                #pragma unroll
                for (int nt = 0; nt < 4; nt++) {
                    asm volatile(
                        "mma.sync.aligned.m16n8k16.row.col.f32.bf16.bf16.f32 "
                        "{%0,%1,%2,%3}, {%4,%5,%6,%7}, {%8,%9}, {%0,%1,%2,%3};"
                        : "+f"(acc[mt][nt][0]), "+f"(acc[mt][nt][1]),
                          "+f"(acc[mt][nt][2]), "+f"(acc[mt][nt][3])
                        : "r"(a0), "r"(a1), "r"(a2), "r"(a3),
                          "r"(b[nt][0]), "r"(b[nt][1]));
                }
            }
        }
        buf ^= 1;
    }
    #pragma unroll
    for (int mt = 0; mt < 4; mt++) {
        #pragma unroll
        for (int nt = 0; nt < 4; nt++) {
            int r = row0 + wm + mt * 16 + gid;
            int c = col0 + wn + nt * 8 + tig * 2;
            if (c < WROWS) {
                if (r < NN) {
                    g_P[(size_t)r * PSTR + c]     = acc[mt][nt][0];
                    g_P[(size_t)r * PSTR + c + 1] = acc[mt][nt][1];
                }
                if (r + 8 < NN) {
                    g_P[(size_t)(r + 8) * PSTR + c]     = acc[mt][nt][2];
                    g_P[(size_t)(r + 8) * PSTR + c + 1] = acc[mt][nt][3];
                }
            }
        }
    }
}

// ---------------- per-node gate + logit table -------------------------------
__global__ __launch_bounds__(256) void k_post(const float* __restrict__ w2,
                                              const float* __restrict__ b2,
                                              const int* __restrict__ node_types,
                                              int l) {
    int warp = (blockIdx.x * blockDim.x + threadIdx.x) >> 5;
    int lane = threadIdx.x & 31;
    if (warp >= NN) return;
    int n = warp;
    int t = node_types[n];
    const float* Pr = g_P + (size_t)n * PSTR;
    float at[4];
    #pragma unroll
    for (int h = 0; h < 4; h++) {
        float hid = tanhf(Pr[h * 32 + lane] + g_tb[((l * 4 + h) * 3 + t) * 32 + lane]);
        float v = hid * w2[(l * 4 + h) * 32 + lane];
        #pragma unroll
        for (int off = 16; off; off >>= 1) v += __shfl_xor_sync(0xffffffffu, v, off);
        at[h] = 1.f / (1.f + __expf(-(v + b2[l * 4 + h])));
    }
    if (lane < 12) {
        int tt = lane >> 2, h = lane & 3;
        float q = Pr[128 + h * 3 + tt];
        float lr = q > 0.f ? q : 0.2f * q;
        g_s[n * 12 + lane] = lr * at[h];   // [n][t][h]
    }
}

// ---------------- warp-per-edge segment softmax (no atomics) ----------------
__global__ __launch_bounds__(256) void k_soft(const int* __restrict__ ni,
                                              const int* __restrict__ etype) {
    int w = (blockIdx.x * blockDim.x + threadIdx.x) >> 5;
    int lane = threadIdx.x & 31;
    if (w >= EE) return;
    int e = w;
    int beg = g_eoff[e], deg = g_eoff[e + 1] - beg;
    if (deg == 0) return;
    int et = etype[e];
    int pi = lane >> 2, h = lane & 3;
    float mx = -INFINITY;
    for (int i0 = 0; i0 < deg; i0 += 8) {
        int i = i0 + pi;
        if (i < deg) {
            int m = g_elist[beg + i];
            float a = g_s[ni[m] * 12 + et * 4 + h];
            mx = fmaxf(mx, a);
        }
    }
    #pragma unroll
    for (int o = 4; o < 32; o <<= 1) mx = fmaxf(mx, __shfl_xor_sync(0xffffffffu, mx, o));
    float den = 0.f;
    for (int i0 = 0; i0 < deg; i0 += 8) {
        int i = i0 + pi;
        if (i < deg) {
            int m = g_elist[beg + i];
            float a = g_s[ni[m] * 12 + et * 4 + h];
            float ex = __expf(a - mx);
            g_alpha[(size_t)m * 4 + h] = ex;
            den += ex;
        }
    }
    #pragma unroll
    for (int o = 4; o < 32; o <<= 1) den += __shfl_xor_sync(0xffffffffu, den, o);
    float inv = 1.f / den;
    for (int i0 = 0; i0 < deg; i0 += 8) {
        int i = i0 + pi;
        if (i < deg) {
            int m = g_elist[beg + i];
            g_alpha[(size_t)m * 4 + h] *= inv;
        }
    }
}

// ---------------- block-per-edge gather, float4 vectorized ------------------
// 256 threads = 4 pair-slices (p) x 64 float4 columns (c). Each thread loads
// 16B of the gathered V row; slices process interleaved pairs; 4-way smem
// reduction at the end.
__global__ __launch_bounds__(256) void k_edge(const int* __restrict__ ni) {
    int e = blockIdx.x;
    int tid = threadIdx.x;
    int p = tid >> 6, c = tid & 63;
    int hq = c >> 4;                       // head for this float4 column
    __shared__ int   s_m[32];
    __shared__ int   s_node[32];
    __shared__ float s_a[32][4];
    __shared__ float4 s_red[4][64];
    int beg = g_eoff[e], end = g_eoff[e + 1];
    float4 acc = make_float4(0.f, 0.f, 0.f, 0.f);
    for (int c0 = beg; c0 < end; c0 += 32) {
        int cnt = min(32, end - c0);
        if (tid < cnt) {
            int m = g_elist[c0 + tid];
            s_m[tid] = m;
            s_node[tid] = ni[m];
        }
        __syncthreads();
        if (tid < cnt * 4) s_a[tid >> 2][tid & 3] = g_alpha[(size_t)s_m[tid >> 2] * 4 + (tid & 3)];
        __syncthreads();
        #pragma unroll 2
        for (int i = p; i < cnt; i += 4) {
            float a = s_a[i][hq];
            float4 v = *(const float4*)(g_P + (size_t)s_node[i] * PSTR + VOFF + 4 * c);
            acc.x += a * v.x; acc.y += a * v.y; acc.z += a * v.z; acc.w += a * v.w;
        }
        __syncthreads();
    }
    s_red[p][c] = acc;
    __syncthreads();
    if (p == 0) {
        float4 r0 = s_red[0][c], r1 = s_red[1][c], r2 = s_red[2][c], r3 = s_red[3][c];
        r0.x += r1.x + r2.x + r3.x;
        r0.y += r1.y + r2.y + r3.y;
        r0.z += r1.z + r2.z + r3.z;
        r0.w += r1.w + r2.w + r3.w;
        *(float4*)(g_edge + (size_t)e * 256 + 4 * c) = r0;
    }
}

// ---------------- block-per-node gather + residual + LayerNorm (float4) -----
__global__ __launch_bounds__(256) void k_node_ln(const int* __restrict__ ei,
                                                 const float* __restrict__ hin,
                                                 const float* __restrict__ gma,
                                                 const float* __restrict__ bet,
                                                 float* __restrict__ outf,
                                                 __nv_bfloat16* __restrict__ outb) {
    int n = blockIdx.x;
    int tid = threadIdx.x;
    int p = tid >> 6, c = tid & 63;
    int hq = c >> 4;
    __shared__ int   s_m[32];
    __shared__ int   s_e[32];
    __shared__ float s_a[32][4];
    __shared__ float4 s_red[4][64];
    __shared__ float red[8];
    int beg = g_noff[n], end = g_noff[n + 1];
    float4 acc = make_float4(0.f, 0.f, 0.f, 0.f);
    for (int c0 = beg; c0 < end; c0 += 32) {
        int cnt = min(32, end - c0);
        if (tid < cnt) {
            int m = g_nlist[c0 + tid];
            s_m[tid] = m;
            s_e[tid] = ei[m];
        }
        __syncthreads();
        if (tid < cnt * 4) s_a[tid >> 2][tid & 3] = g_alpha[(size_t)s_m[tid >> 2] * 4 + (tid & 3)];
        __syncthreads();
        #pragma unroll 2
        for (int i = p; i < cnt; i += 4) {
            float a = s_a[i][hq];
            float4 v = *(const float4*)(g_edge + (size_t)s_e[i] * 256 + 4 * c);
            acc.x += a * v.x; acc.y += a * v.y; acc.z += a * v.z; acc.w += a * v.w;
        }
        __syncthreads();
    }
    s_red[p][c] = acc;
    __syncthreads();
    // final 256-vector staged in s_red[0]
    if (p == 0) {
        float4 r0 = s_red[0][c], r1 = s_red[1][c], r2 = s_red[2][c], r3 = s_red[3][c];
        r0.x += r1.x + r2.x + r3.x;
        r0.y += r1.y + r2.y + r3.y;
        r0.z += r1.z + r2.z + r3.z;
        r0.w += r1.w + r2.w + r3.w;
        s_red[0][c] = r0;
    }
    __syncthreads();
    float v = hin[(size_t)n * 256 + tid] + ((const float*)s_red[0])[tid];
    float s = v;
    #pragma unroll
    for (int o = 16; o; o >>= 1) s += __shfl_xor_sync(0xffffffffu, s, o);
    if ((tid & 31) == 0) red[tid >> 5] = s;
    __syncthreads();
    float mu = 0.f;
    #pragma unroll
    for (int k = 0; k < 8; k++) mu += red[k];
    mu *= (1.f / 256.f);
    __syncthreads();
    float d = v - mu;
    float s2 = d * d;
    #pragma unroll
    for (int o = 16; o; o >>= 1) s2 += __shfl_xor_sync(0xffffffffu, s2, o);
    if ((tid & 31) == 0) red[tid >> 5] = s2;
    __syncthreads();
    float var = 0.f;
    #pragma unroll
    for (int k = 0; k < 8; k++) var += red[k];
    float rstd = rsqrtf(var * (1.f / 256.f) + 1e-5f);
    float r = d * rstd * gma[tid] + bet[tid];
    outf[(size_t)n * 256 + tid] = r;
    if (outb) outb[(size_t)n * 256 + tid] = __float2bfloat16(r);
}

// ---------------- host ------------------------------------------------------
extern "C" void kernel_launch(void* const* d_in, const int* in_sizes, int n_in,
                              void* d_out, int out_size) {
    const float* x         = (const float*)d_in[0];
    const int*   node_types= (const int*)  d_in[1];
    const int*   edge_type = (const int*)  d_in[2];
    const int*   node_idx  = (const int*)  d_in[3];
    const int*   edge_idx  = (const int*)  d_in[4];
    const float* tq        = (const float*)d_in[5];
    const float* w1        = (const float*)d_in[6];
    const float* b1        = (const float*)d_in[7];
    const float* w2        = (const float*)d_in[8];
    const float* b2        = (const float*)d_in[9];
    const float* wq        = (const float*)d_in[10];
    const float* wv        = (const float*)d_in[11];
    const float* ec        = (const float*)d_in[12];
    const float* ln_g      = (const float*)d_in[13];
    const float* ln_b      = (const float*)d_in[14];
    float* out = (float*)d_out;

    static bool attr_set = false;
    if (!attr_set) {
        cudaFuncSetAttribute(k_gemm, cudaFuncAttributeMaxDynamicSharedMemorySize,
                             GEMM_SMEM_BYTES);
        attr_set = true;
    }

    void *pedeg, *pndeg, *pecur, *pncur, *peoff, *pnoff, *pepart, *pnpart, *ph, *phb;
    cudaGetSymbolAddress(&pedeg,  g_edeg);
    cudaGetSymbolAddress(&pndeg,  g_ndeg);
    cudaGetSymbolAddress(&pecur,  g_ecur);
    cudaGetSymbolAddress(&pncur,  g_ncur);
    cudaGetSymbolAddress(&peoff,  g_eoff);
    cudaGetSymbolAddress(&pnoff,  g_noff);
    cudaGetSymbolAddress(&pepart, g_epart);
    cudaGetSymbolAddress(&pnpart, g_npart);
    cudaGetSymbolAddress(&ph,     g_h);
    cudaGetSymbolAddress(&phb,    g_hb);
    const float* hbuf = (const float*)ph;
    __nv_bfloat16* hbbuf = (__nv_bfloat16*)phb;

    cudaMemsetAsync(pedeg, 0, EE * 4);
    cudaMemsetAsync(pndeg, 0, NN * 4);
    cudaMemsetAsync(pecur, 0, EE * 4);
    cudaMemsetAsync(pncur, 0, NN * 4);

    const int NB_E = (EE + 1023) / 1024;
    const int NB_N = (NN + 1023) / 1024;
    dim3 gg((WROWS + GBN - 1) / GBN, (NN + GBM - 1) / GBM);

    k_cvt<<<(NN * 64 + 255) / 256, 256>>>(x);
    k_prep_wcat<<<(2 * WROWS * 256 + 255) / 256, 256>>>(w1, wq, wv, ec);
    k_prep_tb<<<3, 256>>>(b1, tq, w1);

    for (int l = 0; l < 2; l++) {
        const float* hin = l ? hbuf : x;
        k_gemm<<<gg, 256, GEMM_SMEM_BYTES>>>(hbbuf, l);
        if (l == 0) {
            k_deg<<<MM / 256, 256>>>(node_idx, edge_idx);
            k_scan1<<<NB_E, 1024>>>((const int*)pedeg, (int*)peoff, (int*)pepart, EE);
            k_scan1<<<NB_N, 1024>>>((const int*)pndeg, (int*)pnoff, (int*)pnpart, NN);
            k_scan2<<<1, 32>>>((int*)pepart, NB_E);
            k_scan2<<<1, 32>>>((int*)pnpart, NB_N);
            k_scan3<<<NB_E, 1024>>>((int*)peoff, (const int*)pepart, EE, NB_E);
            k_scan3<<<NB_N, 1024>>>((int*)pnoff, (const int*)pnpart, NN, NB_N);
            k_fill<<<MM / 256, 256>>>(node_idx, edge_idx);
        }
        k_post<<<(NN + 7) / 8, 256>>>(w2, b2, node_types, l);
        k_soft<<<(EE + 7) / 8, 256>>>(node_idx, edge_type);
        k_edge<<<EE, 256>>>(node_idx);
        k_node_ln<<<NN, 256>>>(edge_idx, hin, ln_g + l * 256, ln_b + l * 256,
                               l ? out : (float*)ph,
                               l ? (__nv_bfloat16*)nullptr : hbbuf);
    }
}

// round 16
// speedup vs baseline: 3.3245x; 1.7363x over previous
#include <cuda_runtime.h>
#include <cuda_bf16.h>
#include <math.h>
#include <stdint.h>

#define NN 50000
#define EE 20000
#define MM 320000
#define WROWS 396   // 128 (gate MLP) + 12 (wqe) + 256 (V)
#define PSTR 144    // padded row stride of P (gate+wqe only now)
#define VOFF 140    // V columns start at 140 in Wcat

// ---------------- scratch (device globals) ----------------------------------
__device__ float          g_P[(size_t)NN * PSTR];      // gate-MLP + wqe columns
__device__ __nv_bfloat16  g_Vb[(size_t)NN * 256];      // V projections (bf16)
__device__ float          g_s[NN * 12];                // gated logits [n][t][h]
__device__ float          g_alpha[MM * 4];             // ex per pair
__device__ float          g_den[EE * 4];               // softmax denominators
__device__ float          g_edge[(size_t)EE * 256];    // edge features
__device__ float          g_h[(size_t)NN * 256];       // fp32 hidden (residual)
__device__ __nv_bfloat16  g_hb[(size_t)NN * 256];      // bf16 mirror for GEMM
__device__ __nv_bfloat16  g_wcatb[2 * WROWS * 256];    // folded weights (bf16)
__device__ float          g_tb[2 * 4 * 3 * 32];
// CSR scratch
__device__ int g_edeg[EE], g_eoff[EE + 1], g_ecur[EE], g_elist[MM], g_epart[64];
__device__ int g_ndeg[NN], g_noff[NN + 1], g_ncur[NN], g_nlist[MM], g_npart[64];

// ---------------- helpers ---------------------------------------------------
__device__ __forceinline__ void cpa16(void* smem, const void* gmem, bool valid) {
    uint32_t s = (uint32_t)__cvta_generic_to_shared(smem);
    int sz = valid ? 16 : 0;
    asm volatile("cp.async.ca.shared.global [%0], [%1], 16, %2;"
                 :: "r"(s), "l"(gmem), "r"(sz));
}
__device__ __forceinline__ float fast_tanh(float x) {
    float r;
    asm("tanh.approx.f32 %0, %1;" : "=f"(r) : "f"(x));
    return r;
}

// ---------------- input conversion ------------------------------------------
__global__ void k_cvt(const float* __restrict__ x) {
    int id = blockIdx.x * blockDim.x + threadIdx.x;
    if (id >= NN * 64) return;
    float4 v = *(const float4*)(x + (size_t)id * 4);
    __nv_bfloat16* d = g_hb + (size_t)id * 4;
    d[0] = __float2bfloat16(v.x); d[1] = __float2bfloat16(v.y);
    d[2] = __float2bfloat16(v.z); d[3] = __float2bfloat16(v.w);
}

// ---------------- weight folding --------------------------------------------
__global__ void k_prep_wcat(const float* __restrict__ w1, const float* __restrict__ wq,
                            const float* __restrict__ wv, const float* __restrict__ ec) {
    int id = blockIdx.x * blockDim.x + threadIdx.x;
    if (id >= 2 * WROWS * 256) return;
    int d = id & 255;
    int r = (id >> 8) % WROWS;
    int l = id / (WROWS * 256);
    float val;
    if (r < 128) {
        int h = r >> 5, k = r & 31;
        val = w1[(((l * 4 + h) * 32 + k) * 320) + d];
    } else if (r < 140) {
        int rr = r - 128, h = rr / 3, t = rr % 3;
        const float* wqp = wq + ((size_t)(l * 4 + h) * 64) * 256 + d;
        const float* ecp = ec + ((l * 4 + h) * 3 + t) * 64;
        float acc = 0.f;
        #pragma unroll 8
        for (int o = 0; o < 64; o++) acc += wqp[(size_t)o * 256] * ecp[o];
        val = acc;
    } else {
        int rr = r - 140, h = rr >> 6, o = rr & 63;
        val = wv[((size_t)((l * 4 + h) * 64 + o)) * 256 + d];
    }
    g_wcatb[(size_t)(l * WROWS + r) * 256 + d] = __float2bfloat16(val);
}

__global__ void k_prep_tb(const float* __restrict__ b1, const float* __restrict__ tq,
                          const float* __restrict__ w1) {
    int id = blockIdx.x * blockDim.x + threadIdx.x;
    if (id >= 2 * 4 * 3 * 32) return;
    int k = id & 31;
    int rem = id >> 5;
    int t = rem % 3;
    int lh = rem / 3;
    float acc = b1[lh * 32 + k];
    const float* tqp = tq + (lh * 3 + t) * 64;
    const float* w1p = w1 + ((size_t)(lh * 32 + k)) * 320 + 256;
    #pragma unroll 8
    for (int d = 0; d < 64; d++) acc += tqp[d] * w1p[d];
    g_tb[id] = acc;
}

// ---------------- CSR construction ------------------------------------------
__global__ void k_deg(const int* __restrict__ ni, const int* __restrict__ ei) {
    int m = blockIdx.x * blockDim.x + threadIdx.x;
    if (m >= MM) return;
    atomicAdd(&g_edeg[ei[m]], 1);
    atomicAdd(&g_ndeg[ni[m]], 1);
}

__global__ __launch_bounds__(1024) void k_scan1(const int* __restrict__ deg,
                                                int* __restrict__ out,
                                                int* __restrict__ part, int n) {
    __shared__ int ws[32];
    int tid = threadIdx.x, lane = tid & 31, wid = tid >> 5;
    int i = blockIdx.x * 1024 + tid;
    int v = (i < n) ? deg[i] : 0;
    int s = v;
    #pragma unroll
    for (int o = 1; o < 32; o <<= 1) {
        int t = __shfl_up_sync(0xffffffffu, s, o);
        if (lane >= o) s += t;
    }
    if (lane == 31) ws[wid] = s;
    __syncthreads();
    if (wid == 0) {
        int t = ws[lane];
        #pragma unroll
        for (int o = 1; o < 32; o <<= 1) {
            int u = __shfl_up_sync(0xffffffffu, t, o);
            if (lane >= o) t += u;
        }
        ws[lane] = t;
    }
    __syncthreads();
    int incl = s + (wid ? ws[wid - 1] : 0);
    if (i < n) out[i] = incl - v;
    if (tid == 1023) part[blockIdx.x] = incl;
}

__global__ void k_scan2(int* part, int nb) {
    if (threadIdx.x != 0) return;
    int acc = 0;
    for (int b = 0; b < nb; b++) {
        int v = part[b];
        part[b] = acc;
        acc += v;
    }
    part[nb] = acc;
}

__global__ __launch_bounds__(1024) void k_scan3(int* __restrict__ off,
                                                const int* __restrict__ part,
                                                int n, int nb) {
    int i = blockIdx.x * 1024 + threadIdx.x;
    if (i < n) off[i] += part[i >> 10];
    if (i == 0) off[n] = part[nb];
}

__global__ void k_fill(const int* __restrict__ ni, const int* __restrict__ ei) {
    int m = blockIdx.x * blockDim.x + threadIdx.x;
    if (m >= MM) return;
    int e = ei[m];
    int p = atomicAdd(&g_ecur[e], 1);
    g_elist[g_eoff[e] + p] = m;
    int n = ni[m];
    int q = atomicAdd(&g_ncur[n], 1);
    g_nlist[g_noff[n] + q] = m;
}

// ---------------- bf16 GEMM: P|V = h x Wcat^T --------------------------------
#define GBM 256
#define GBN 64
#define GBK 64
#define SKPB 72
#define SMA (GBM * SKPB)
#define SMB (GBN * SKPB)
#define GEMM_SMEM_BYTES ((2 * SMA + 2 * SMB) * 2)

__global__ __launch_bounds__(256) void k_gemm(const __nv_bfloat16* __restrict__ A,
                                              int layer) {
    extern __shared__ __nv_bfloat16 smb[];
    __nv_bfloat16* As = smb;
    __nv_bfloat16* Bs = smb + 2 * SMA;
    const __nv_bfloat16* Bg = g_wcatb + (size_t)layer * WROWS * 256;
    int tid = threadIdx.x;
    int row0 = blockIdx.y * GBM;
    int col0 = blockIdx.x * GBN;
    int warp = tid >> 5, lane = tid & 31;
    int gid = lane >> 2, tig = lane & 3;
    int wm = (warp >> 1) * 64;
    int wn = (warp & 1) * 32;
    int lr = tid >> 3;
    int lcb = (tid & 7) * 8;
    float acc[4][4][4] = {};

    auto load_stage = [&](int s, int k0) {
        __nv_bfloat16* Ad = As + s * SMA;
        __nv_bfloat16* Bd = Bs + s * SMB;
        #pragma unroll
        for (int p = 0; p < 8; p++) {
            int r = row0 + p * 32 + lr;
            cpa16(&Ad[(p * 32 + lr) * SKPB + lcb], A + (size_t)r * 256 + k0 + lcb, r < NN);
        }
        #pragma unroll
        for (int p = 0; p < 2; p++) {
            int r = col0 + p * 32 + lr;
            cpa16(&Bd[(p * 32 + lr) * SKPB + lcb], Bg + (size_t)r * 256 + k0 + lcb, r < WROWS);
        }
    };

    load_stage(0, 0);
    asm volatile("cp.async.commit_group;");
    int buf = 0;
    #pragma unroll 1
    for (int it = 0; it < 4; it++) {
        asm volatile("cp.async.wait_group 0;");
        __syncthreads();
        if (it < 3) {
            load_stage(buf ^ 1, (it + 1) * GBK);
            asm volatile("cp.async.commit_group;");
        }
        const __nv_bfloat16* Ab = As + buf * SMA;
        const __nv_bfloat16* Bb = Bs + buf * SMB;
        #pragma unroll
        for (int kc = 0; kc < 4; kc++) {
            int kk = kc * 16;
            uint32_t b[4][2];
            #pragma unroll
            for (int nt = 0; nt < 4; nt++) {
                int n = wn + nt * 8 + gid;
                b[nt][0] = *(const uint32_t*)&Bb[n * SKPB + kk + 2 * tig];
                b[nt][1] = *(const uint32_t*)&Bb[n * SKPB + kk + 2 * tig + 8];
            }
            #pragma unroll
            for (int mt = 0; mt < 4; mt++) {
                int m = wm + mt * 16 + gid;
                uint32_t a0 = *(const uint32_t*)&Ab[m * SKPB + kk + 2 * tig];
                uint32_t a1 = *(const uint32_t*)&Ab[(m + 8) * SKPB + kk + 2 * tig];
                uint32_t a2 = *(const uint32_t*)&Ab[m * SKPB + kk + 2 * tig + 8];
                uint32_t a3 = *(const uint32_t*)&Ab[(m + 8) * SKPB + kk + 2 * tig + 8];
                #pragma unroll
                for (int nt = 0; nt < 4; nt++) {
                    asm volatile(
                        "mma.sync.aligned.m16n8k16.row.col.f32.bf16.bf16.f32 "
                        "{%0,%1,%2,%3}, {%4,%5,%6,%7}, {%8,%9}, {%0,%1,%2,%3};"
                        : "+f"(acc[mt][nt][0]), "+f"(acc[mt][nt][1]),
                          "+f"(acc[mt][nt][2]), "+f"(acc[mt][nt][3])
                        : "r"(a0), "r"(a1), "r"(a2), "r"(a3),
                          "r"(b[nt][0]), "r"(b[nt][1]));
                }
            }
        }
        buf ^= 1;
    }
    #pragma unroll
    for (int mt = 0; mt < 4; mt++) {
        #pragma unroll
        for (int nt = 0; nt < 4; nt++) {
            int c = col0 + wn + nt * 8 + tig * 2;
            if (c >= WROWS) continue;
            #pragma unroll
            for (int half = 0; half < 2; half++) {
                int r = row0 + wm + mt * 16 + gid + half * 8;
                if (r >= NN) continue;
                float v0 = acc[mt][nt][half * 2 + 0];
                float v1 = acc[mt][nt][half * 2 + 1];
                if (c < VOFF) {   // c even, pair stays below 140
                    g_P[(size_t)r * PSTR + c]     = v0;
                    g_P[(size_t)r * PSTR + c + 1] = v1;
                } else {
                    int vc = c - VOFF;
                    __nv_bfloat162 bv = __floats2bfloat162_rn(v0, v1);
                    *(__nv_bfloat162*)(g_Vb + (size_t)r * 256 + vc) = bv;
                }
            }
        }
    }
}

// ---------------- per-node gate + logit table -------------------------------
__global__ __launch_bounds__(256) void k_post(const float* __restrict__ w2,
                                              const float* __restrict__ b2,
                                              const int* __restrict__ node_types,
                                              int l) {
    int warp = (blockIdx.x * blockDim.x + threadIdx.x) >> 5;
    int lane = threadIdx.x & 31;
    if (warp >= NN) return;
    int n = warp;
    int t = node_types[n];
    const float* Pr = g_P + (size_t)n * PSTR;
    float at[4];
    #pragma unroll
    for (int h = 0; h < 4; h++) {
        float hid = fast_tanh(Pr[h * 32 + lane] + g_tb[((l * 4 + h) * 3 + t) * 32 + lane]);
        float v = hid * w2[(l * 4 + h) * 32 + lane];
        #pragma unroll
        for (int off = 16; off; off >>= 1) v += __shfl_xor_sync(0xffffffffu, v, off);
        at[h] = 1.f / (1.f + __expf(-(v + b2[l * 4 + h])));
    }
    if (lane < 12) {
        int tt = lane >> 2, h = lane & 3;
        float q = Pr[128 + h * 3 + tt];
        float lr = q > 0.f ? q : 0.2f * q;
        g_s[n * 12 + lane] = lr * at[h];   // [n][t][h]
    }
}

// ---------------- fused softmax + edge gather (warp per edge) ----------------
// exp without max-subtract (logits bounded, softmax shift-invariant).
// Lane owns 8 consecutive columns (head h = lane>>3).
__global__ __launch_bounds__(256) void k_edge(const int* __restrict__ ni,
                                              const int* __restrict__ etype) {
    int e = (blockIdx.x * blockDim.x + threadIdx.x) >> 5;
    int lane = threadIdx.x & 31;
    if (e >= EE) return;
    int beg = g_eoff[e], deg = g_eoff[e + 1] - beg;
    if (deg == 0) return;
    int et = etype[e];
    int h = lane >> 3;
    float den = 0.f;
    float acc[8] = {};
    for (int c0 = 0; c0 < deg; c0 += 32) {
        int cnt = min(32, deg - c0);
        int node = 0;
        float4 ex4 = make_float4(0.f, 0.f, 0.f, 0.f);
        if (lane < cnt) {
            int m = g_elist[beg + c0 + lane];
            node = ni[m];
            float4 s4 = *(const float4*)(g_s + node * 12 + et * 4);
            ex4.x = __expf(s4.x); ex4.y = __expf(s4.y);
            ex4.z = __expf(s4.z); ex4.w = __expf(s4.w);
            *(float4*)(g_alpha + (size_t)m * 4) = ex4;
        }
        #pragma unroll 4
        for (int i = 0; i < cnt; i++) {
            int nd = __shfl_sync(0xffffffffu, node, i);
            float e0 = __shfl_sync(0xffffffffu, ex4.x, i);
            float e1 = __shfl_sync(0xffffffffu, ex4.y, i);
            float e2 = __shfl_sync(0xffffffffu, ex4.z, i);
            float e3 = __shfl_sync(0xffffffffu, ex4.w, i);
            float exh = (h == 0) ? e0 : (h == 1) ? e1 : (h == 2) ? e2 : e3;
            den += exh;
            uint4 raw = *(const uint4*)(g_Vb + (size_t)nd * 256 + lane * 8);
            acc[0] += exh * __uint_as_float(raw.x << 16);
            acc[1] += exh * __uint_as_float(raw.x & 0xffff0000u);
            acc[2] += exh * __uint_as_float(raw.y << 16);
            acc[3] += exh * __uint_as_float(raw.y & 0xffff0000u);
            acc[4] += exh * __uint_as_float(raw.z << 16);
            acc[5] += exh * __uint_as_float(raw.z & 0xffff0000u);
            acc[6] += exh * __uint_as_float(raw.w << 16);
            acc[7] += exh * __uint_as_float(raw.w & 0xffff0000u);
        }
    }
    float inv = 1.f / den;
    float* dst = g_edge + (size_t)e * 256 + lane * 8;
    *(float4*)dst       = make_float4(acc[0] * inv, acc[1] * inv, acc[2] * inv, acc[3] * inv);
    *(float4*)(dst + 4) = make_float4(acc[4] * inv, acc[5] * inv, acc[6] * inv, acc[7] * inv);
    if ((lane & 7) == 0) g_den[e * 4 + h] = den;
}

// ---------------- warp-per-node gather + residual + LayerNorm ---------------
__global__ __launch_bounds__(256) void k_node_ln(const int* __restrict__ ei,
                                                 const float* __restrict__ hin,
                                                 const float* __restrict__ gma,
                                                 const float* __restrict__ bet,
                                                 float* __restrict__ outf,
                                                 __nv_bfloat16* __restrict__ outb) {
    int n = (blockIdx.x * blockDim.x + threadIdx.x) >> 5;
    int lane = threadIdx.x & 31;
    if (n >= NN) return;
    int beg = g_noff[n], deg = g_noff[n + 1] - beg;
    int h = lane >> 3;
    float acc[8] = {};
    for (int c0 = 0; c0 < deg; c0 += 32) {
        int cnt = min(32, deg - c0);
        int eidx = 0;
        float4 at4 = make_float4(0.f, 0.f, 0.f, 0.f);
        if (lane < cnt) {
            int m = g_nlist[beg + c0 + lane];
            eidx = ei[m];
            float4 ex4 = *(const float4*)(g_alpha + (size_t)m * 4);
            float4 d4  = *(const float4*)(g_den + eidx * 4);
            at4.x = ex4.x / d4.x; at4.y = ex4.y / d4.y;
            at4.z = ex4.z / d4.z; at4.w = ex4.w / d4.w;
        }
        #pragma unroll 4
        for (int i = 0; i < cnt; i++) {
            int ee = __shfl_sync(0xffffffffu, eidx, i);
            float a0 = __shfl_sync(0xffffffffu, at4.x, i);
            float a1 = __shfl_sync(0xffffffffu, at4.y, i);
            float a2 = __shfl_sync(0xffffffffu, at4.z, i);
            float a3 = __shfl_sync(0xffffffffu, at4.w, i);
            float at = (h == 0) ? a0 : (h == 1) ? a1 : (h == 2) ? a2 : a3;
            const float* Er = g_edge + (size_t)ee * 256 + lane * 8;
            float4 v0 = *(const float4*)Er;
            float4 v1 = *(const float4*)(Er + 4);
            acc[0] += at * v0.x; acc[1] += at * v0.y;
            acc[2] += at * v0.z; acc[3] += at * v0.w;
            acc[4] += at * v1.x; acc[5] += at * v1.y;
            acc[6] += at * v1.z; acc[7] += at * v1.w;
        }
    }
    // residual + LayerNorm (warp-level, 8 values per lane)
    size_t base = (size_t)n * 256 + lane * 8;
    float4 h0 = *(const float4*)(hin + base);
    float4 h1 = *(const float4*)(hin + base + 4);
    float v[8];
    v[0] = h0.x + acc[0]; v[1] = h0.y + acc[1]; v[2] = h0.z + acc[2]; v[3] = h0.w + acc[3];
    v[4] = h1.x + acc[4]; v[5] = h1.y + acc[5]; v[6] = h1.z + acc[6]; v[7] = h1.w + acc[7];
    float s = 0.f;
    #pragma unroll
    for (int k = 0; k < 8; k++) s += v[k];
    #pragma unroll
    for (int o = 16; o; o >>= 1) s += __shfl_xor_sync(0xffffffffu, s, o);
    float mu = s * (1.f / 256.f);
    float s2 = 0.f;
    #pragma unroll
    for (int k = 0; k < 8; k++) { float d = v[k] - mu; s2 += d * d; }
    #pragma unroll
    for (int o = 16; o; o >>= 1) s2 += __shfl_xor_sync(0xffffffffu, s2, o);
    float rstd = rsqrtf(s2 * (1.f / 256.f) + 1e-5f);
    float4 g0 = *(const float4*)(gma + lane * 8);
    float4 g1 = *(const float4*)(gma + lane * 8 + 4);
    float4 b0 = *(const float4*)(bet + lane * 8);
    float4 b1 = *(const float4*)(bet + lane * 8 + 4);
    float r[8];
    r[0] = (v[0] - mu) * rstd * g0.x + b0.x;
    r[1] = (v[1] - mu) * rstd * g0.y + b0.y;
    r[2] = (v[2] - mu) * rstd * g0.z + b0.z;
    r[3] = (v[3] - mu) * rstd * g0.w + b0.w;
    r[4] = (v[4] - mu) * rstd * g1.x + b1.x;
    r[5] = (v[5] - mu) * rstd * g1.y + b1.y;
    r[6] = (v[6] - mu) * rstd * g1.z + b1.z;
    r[7] = (v[7] - mu) * rstd * g1.w + b1.w;
    *(float4*)(outf + base)     = make_float4(r[0], r[1], r[2], r[3]);
    *(float4*)(outf + base + 4) = make_float4(r[4], r[5], r[6], r[7]);
    if (outb) {
        __nv_bfloat162 q0 = __floats2bfloat162_rn(r[0], r[1]);
        __nv_bfloat162 q1 = __floats2bfloat162_rn(r[2], r[3]);
        __nv_bfloat162 q2 = __floats2bfloat162_rn(r[4], r[5]);
        __nv_bfloat162 q3 = __floats2bfloat162_rn(r[6], r[7]);
        uint4 pk = make_uint4(*(uint32_t*)&q0, *(uint32_t*)&q1,
                              *(uint32_t*)&q2, *(uint32_t*)&q3);
        *(uint4*)(outb + base) = pk;
    }
}

// ---------------- host ------------------------------------------------------
extern "C" void kernel_launch(void* const* d_in, const int* in_sizes, int n_in,
                              void* d_out, int out_size) {
    const float* x         = (const float*)d_in[0];
    const int*   node_types= (const int*)  d_in[1];
    const int*   edge_type = (const int*)  d_in[2];
    const int*   node_idx  = (const int*)  d_in[3];
    const int*   edge_idx  = (const int*)  d_in[4];
    const float* tq        = (const float*)d_in[5];
    const float* w1        = (const float*)d_in[6];
    const float* b1        = (const float*)d_in[7];
    const float* w2        = (const float*)d_in[8];
    const float* b2        = (const float*)d_in[9];
    const float* wq        = (const float*)d_in[10];
    const float* wv        = (const float*)d_in[11];
    const float* ec        = (const float*)d_in[12];
    const float* ln_g      = (const float*)d_in[13];
    const float* ln_b      = (const float*)d_in[14];
    float* out = (float*)d_out;

    static bool attr_set = false;
    if (!attr_set) {
        cudaFuncSetAttribute(k_gemm, cudaFuncAttributeMaxDynamicSharedMemorySize,
                             GEMM_SMEM_BYTES);
        attr_set = true;
    }

    void *pedeg, *pndeg, *pecur, *pncur, *peoff, *pnoff, *pepart, *pnpart, *ph, *phb;
    cudaGetSymbolAddress(&pedeg,  g_edeg);
    cudaGetSymbolAddress(&pndeg,  g_ndeg);
    cudaGetSymbolAddress(&pecur,  g_ecur);
    cudaGetSymbolAddress(&pncur,  g_ncur);
    cudaGetSymbolAddress(&peoff,  g_eoff);
    cudaGetSymbolAddress(&pnoff,  g_noff);
    cudaGetSymbolAddress(&pepart, g_epart);
    cudaGetSymbolAddress(&pnpart, g_npart);
    cudaGetSymbolAddress(&ph,     g_h);
    cudaGetSymbolAddress(&phb,    g_hb);
    const float* hbuf = (const float*)ph;
    __nv_bfloat16* hbbuf = (__nv_bfloat16*)phb;

    cudaMemsetAsync(pedeg, 0, EE * 4);
    cudaMemsetAsync(pndeg, 0, NN * 4);
    cudaMemsetAsync(pecur, 0, EE * 4);
    cudaMemsetAsync(pncur, 0, NN * 4);

    const int NB_E = (EE + 1023) / 1024;
    const int NB_N = (NN + 1023) / 1024;
    dim3 gg((WROWS + GBN - 1) / GBN, (NN + GBM - 1) / GBM);

    k_cvt<<<(NN * 64 + 255) / 256, 256>>>(x);
    k_prep_wcat<<<(2 * WROWS * 256 + 255) / 256, 256>>>(w1, wq, wv, ec);
    k_prep_tb<<<3, 256>>>(b1, tq, w1);

    for (int l = 0; l < 2; l++) {
        const float* hin = l ? hbuf : x;
        k_gemm<<<gg, 256, GEMM_SMEM_BYTES>>>(hbbuf, l);
        if (l == 0) {
            k_deg<<<MM / 256, 256>>>(node_idx, edge_idx);
            k_scan1<<<NB_E, 1024>>>((const int*)pedeg, (int*)peoff, (int*)pepart, EE);
            k_scan1<<<NB_N, 1024>>>((const int*)pndeg, (int*)pnoff, (int*)pnpart, NN);
            k_scan2<<<1, 32>>>((int*)pepart, NB_E);
            k_scan2<<<1, 32>>>((int*)pnpart, NB_N);
            k_scan3<<<NB_E, 1024>>>((int*)peoff, (const int*)pepart, EE, NB_E);
            k_scan3<<<NB_N, 1024>>>((int*)pnoff, (const int*)pnpart, NN, NB_N);
            k_fill<<<MM / 256, 256>>>(node_idx, edge_idx);
        }
        k_post<<<(NN + 7) / 8, 256>>>(w2, b2, node_types, l);
        k_edge<<<(EE * 32 + 255) / 256, 256>>>(node_idx, edge_type);
        k_node_ln<<<(NN * 32 + 255) / 256, 256>>>(edge_idx, hin,
                               ln_g + l * 256, ln_b + l * 256,
                               l ? out : (float*)ph,
                               l ? (__nv_bfloat16*)nullptr : hbbuf);
    }
}